// round 14
// baseline (speedup 1.0000x reference)
#include <cuda_runtime.h>
#include <cuda_fp16.h>
#include <math.h>
#include <stdint.h>

#define BSZ    8
#define TT     1000
#define INDIM  256
#define DMODEL 512
#define FFDIM  2048
#define NLAYER 4
#define NHEAD  8
#define DHEAD  64
#define NCLS   8
#define MROWS  (BSZ*TT)   /* 8000 */

// ---------------- scratch (no cudaMalloc allowed) ----------------
__device__ float  g_pool[BSZ * 8 * DMODEL];

__device__ __half g_x16   [MROWS * INDIM];
__device__ __half g_h16   [MROWS * DMODEL];
__device__ __half g_o16   [MROWS * DMODEL];
__device__ __half g_qkv16 [MROWS * 3 * DMODEL];
__device__ __half g_attn16[MROWS * DMODEL];
__device__ __half g_ff16  [MROWS * FFDIM];

__device__ __half g_w16emb[DMODEL * INDIM];
__device__ __half g_w16qkv[NLAYER * 3 * DMODEL * DMODEL];
__device__ __half g_w16o  [NLAYER * DMODEL * DMODEL];
__device__ __half g_w16f1 [NLAYER * FFDIM * DMODEL];
__device__ __half g_w16f2 [NLAYER * DMODEL * FFDIM];

// ======================= helpers =======================
__device__ __forceinline__ uint32_t smem_u32(const void* p) {
    return (uint32_t)__cvta_generic_to_shared(p);
}
__device__ __forceinline__ uint32_t h2_u32(__half2 v) {
    return *reinterpret_cast<uint32_t*>(&v);
}
#define CP_ASYNC16(dst, src, pb) \
    asm volatile("cp.async.cg.shared.global [%0], [%1], 16, %2;\n" \
                 :: "r"(dst), "l"(src), "r"(pb))
#define CP_COMMIT() asm volatile("cp.async.commit_group;\n" ::: "memory")
#define CP_WAIT(n)  asm volatile("cp.async.wait_group %0;\n" :: "n"(n) : "memory")

#define LDSM_X4(r0,r1,r2,r3,addr) \
    asm volatile("ldmatrix.sync.aligned.m8n8.x4.shared.b16 {%0,%1,%2,%3}, [%4];" \
                 : "=r"(r0),"=r"(r1),"=r"(r2),"=r"(r3) : "r"(addr))
#define LDSM_X4T(r0,r1,r2,r3,addr) \
    asm volatile("ldmatrix.sync.aligned.m8n8.x4.trans.shared.b16 {%0,%1,%2,%3}, [%4];" \
                 : "=r"(r0),"=r"(r1),"=r"(r2),"=r"(r3) : "r"(addr))

__device__ __forceinline__ void mma16816(float c[4], uint32_t a0, uint32_t a1,
                                         uint32_t a2, uint32_t a3,
                                         uint32_t b0, uint32_t b1) {
    asm volatile(
        "mma.sync.aligned.m16n8k16.row.col.f32.f16.f16.f32 "
        "{%0,%1,%2,%3}, {%4,%5,%6,%7}, {%8,%9}, {%0,%1,%2,%3};"
        : "+f"(c[0]), "+f"(c[1]), "+f"(c[2]), "+f"(c[3])
        : "r"(a0), "r"(a1), "r"(a2), "r"(a3), "r"(b0), "r"(b1));
}

// ======================= fp16 HMMA GEMM =======================
// flags: 1 = relu, 2 = add sinusoidal PE (embedding). Output always fp16.
// K=64 per stage, 2 stages (73.7 KB smem -> 3 CTAs/SM, 24 warps/SM).
// Two __syncthreads per k-iteration (wait/visible + drain-before-overwrite).
#define ROWB 144
#define STAGE_BYTES (128 * ROWB)          /* 18432 */
#define HG_SMEM (4 * STAGE_BYTES)         /* 73728 */

__global__ __launch_bounds__(256, 3)
void hgemm_kernel(const __half* __restrict__ A, const __half* __restrict__ W,
                  const float* __restrict__ bias, __half* __restrict__ Ch,
                  int M, int N, int K, int flags)
{
    extern __shared__ char smem[];
    const uint32_t sA = smem_u32(smem);
    const uint32_t sB = sA + 2 * STAGE_BYTES;

    const int tid  = threadIdx.x;
    const int wid  = tid >> 5;
    const int lane = tid & 31;
    const int wm = wid >> 2;
    const int wn = wid & 3;
    const int g   = lane >> 2;
    const int tig = lane & 3;
    const int m0 = blockIdx.x * 128;
    const int n0 = blockIdx.y * 128;

    const int nt = K >> 6;

    auto load_tile = [&](int t, int s) {
        const uint32_t da = sA + s * STAGE_BYTES;
        const uint32_t db = sB + s * STAGE_BYTES;
        const __half* Ak = A + t * 64;
        const __half* Wk = W + t * 64;
#pragma unroll
        for (int it = 0; it < 4; it++) {
            int id  = tid + it * 256;
            int row = id >> 3;
            int c   = id & 7;
            int ar = m0 + row; int arc = ar < M ? ar : (M - 1);
            int pa = (ar < M) ? 16 : 0;
            CP_ASYNC16(da + row * ROWB + c * 16,
                       (const char*)(Ak + (size_t)arc * K) + c * 16, pa);
            CP_ASYNC16(db + row * ROWB + c * 16,
                       (const char*)(Wk + (size_t)(n0 + row) * K) + c * 16, 16);
        }
        CP_COMMIT();
    };

    float acc[4][4][4];
#pragma unroll
    for (int i = 0; i < 4; i++)
#pragma unroll
        for (int j = 0; j < 4; j++)
#pragma unroll
            for (int r = 0; r < 4; r++) acc[i][j][r] = 0.f;

    load_tile(0, 0);
    if (nt > 1) load_tile(1, 1);

    const int a_row = (lane & 15);
    const int a_col = (lane >> 4) * 8;
    const int b_row = (lane & 7) + ((lane >> 4) << 3);
    const int b_col = ((lane >> 3) & 1) * 8;

    for (int kt = 0; kt < nt; kt++) {
        if (kt + 1 < nt) { CP_WAIT(1); } else { CP_WAIT(0); }
        __syncthreads();   // tile kt visible to all warps

        const int s = kt & 1;
        const uint32_t baseA = sA + s * STAGE_BYTES;
        const uint32_t baseB = sB + s * STAGE_BYTES;

#pragma unroll
        for (int ks = 0; ks < 4; ks++) {
            const int kk = ks * 16;
            uint32_t bf[4][2];
#pragma unroll
            for (int np = 0; np < 2; np++) {
                uint32_t addr = baseB
                    + (uint32_t)(wn * 32 + np * 16 + b_row) * ROWB
                    + (uint32_t)(kk + b_col) * 2;
                uint32_t b0, b1, b2, b3;
                LDSM_X4(b0, b1, b2, b3, addr);
                bf[np * 2 + 0][0] = b0; bf[np * 2 + 0][1] = b1;
                bf[np * 2 + 1][0] = b2; bf[np * 2 + 1][1] = b3;
            }
#pragma unroll
            for (int mi = 0; mi < 4; mi++) {
                uint32_t addr = baseA
                    + (uint32_t)(wm * 64 + mi * 16 + a_row) * ROWB
                    + (uint32_t)(kk + a_col) * 2;
                uint32_t a0, a1, a2, a3;
                LDSM_X4(a0, a1, a2, a3, addr);
#pragma unroll
                for (int ni = 0; ni < 4; ni++)
                    mma16816(acc[mi][ni], a0, a1, a2, a3, bf[ni][0], bf[ni][1]);
            }
        }

        if (kt + 2 < nt) {
            __syncthreads();   // all warps done reading slot kt&1
            load_tile(kt + 2, s);
        }
    }

    const int relu  = flags & 1;
    const int addpe = flags & 2;
#pragma unroll
    for (int mi = 0; mi < 4; mi++) {
        int gr0 = m0 + wm * 64 + mi * 16 + g;
        int t0r = gr0 % TT, t1r = (gr0 + 8) % TT;
#pragma unroll
        for (int ni = 0; ni < 4; ni++) {
            int gc = n0 + wn * 32 + ni * 8 + 2 * tig;
            float b0 = bias[gc], b1 = bias[gc + 1];
            float v0 = acc[mi][ni][0] + b0;
            float v1 = acc[mi][ni][1] + b1;
            float v2 = acc[mi][ni][2] + b0;
            float v3 = acc[mi][ni][3] + b1;
            if (relu) {
                v0 = fmaxf(v0, 0.f); v1 = fmaxf(v1, 0.f);
                v2 = fmaxf(v2, 0.f); v3 = fmaxf(v3, 0.f);
            }
            if (addpe) {
                float div = expf((float)gc * (-9.210340371976184f / 512.0f));
                float s0, c0, s1, c1;
                sincosf((float)t0r * div, &s0, &c0);
                sincosf((float)t1r * div, &s1, &c1);
                v0 += s0; v1 += c0; v2 += s1; v3 += c1;
            }
            if (gr0 < M)
                *(__half2*)(Ch + (size_t)gr0 * N + gc) = __floats2half2_rn(v0, v1);
            if (gr0 + 8 < M)
                *(__half2*)(Ch + (size_t)(gr0 + 8) * N + gc) = __floats2half2_rn(v2, v3);
        }
    }
}

// ---------------- fused 3-tensor f32 -> f16 convert ----------------
__global__ void cvt3_kernel(const float* __restrict__ s0, __half* __restrict__ d0, int n0,
                            const float* __restrict__ s1, __half* __restrict__ d1, int n1,
                            const float* __restrict__ s2, __half* __restrict__ d2, int n2)
{
    int i = (blockIdx.x * blockDim.x + threadIdx.x) * 4;
    const float* s; __half* d;
    if (i < n0)           { s = s0; d = d0; }
    else if (i < n0 + n1) { s = s1; d = d1; i -= n0; }
    else if (i < n0 + n1 + n2) { s = s2; d = d2; i -= n0 + n1; }
    else return;
    float4 v = *(const float4*)(s + i);
    *(__half2*)(d + i)     = __floats2half2_rn(v.x, v.y);
    *(__half2*)(d + i + 2) = __floats2half2_rn(v.z, v.w);
}

// ================= HMMA banded flash attention (128 q / block) ============
// 3-slot K/V ring, single __syncthreads per tile, per-warp tile skip.
// Heavy heads (large window) scheduled first: hh = 7 - blockIdx.y.
#define AT_STRIDE 72

__global__ __launch_bounds__(256)
void attn_mma_kernel(const __half* __restrict__ qkv, __half* __restrict__ out)
{
    __shared__ __half Qs[128 * AT_STRIDE];
    __shared__ __half Ks[3][32 * AT_STRIDE];
    __shared__ __half Vs[3][32 * AT_STRIDE];

    const int b  = blockIdx.z;
    const int hh = (NHEAD - 1) - blockIdx.y;   // heavy heads first
    const int q0 = blockIdx.x * 128;
    const int tid  = threadIdx.x;
    const int warp = tid >> 5;
    const int lane = tid & 31;
    const int w = 25 * (hh + 1);

    int kstart = q0 - w;       if (kstart < 0) kstart = 0;
    int kend   = q0 + 127 + w; if (kend > TT - 1) kend = TT - 1;
    const int ntiles = (kend - kstart + 32) >> 5;

    const __half* base = qkv + (size_t)(b * TT) * 1536 + hh * 64;

    {
        const uint32_t qdst = smem_u32(Qs);
        for (int i = tid; i < 1024; i += 256) {
            int row = i >> 3, c = i & 7;
            int tq = q0 + row;
            int rc = tq < TT ? tq : (TT - 1);
            int pb = tq < TT ? 16 : 0;
            CP_ASYNC16(qdst + (row * AT_STRIDE + c * 8) * 2,
                       (const char*)(base + (size_t)rc * 1536 + c * 8), pb);
        }
    }
    auto stage_kv = [&](int t, int p) {
        const uint32_t kdst = smem_u32(Ks[p]);
        const uint32_t vdst = smem_u32(Vs[p]);
        const int j0 = kstart + t * 32;
        {
            int i = tid;
            int row = i >> 3, c = i & 7;
            int key = j0 + row;
            int rc = key < TT ? key : (TT - 1);
            int pb = key < TT ? 16 : 0;
            const __half* src = base + (size_t)rc * 1536 + c * 8;
            CP_ASYNC16(kdst + (row * AT_STRIDE + c * 8) * 2, (const char*)(src + 512),  pb);
            CP_ASYNC16(vdst + (row * AT_STRIDE + c * 8) * 2, (const char*)(src + 1024), pb);
        }
        CP_COMMIT();
    };

    stage_kv(0, 0);
    if (ntiles > 1) stage_kv(1, 1);

    const int r0 = lane >> 2;
    const int tq0 = q0 + warp * 16 + r0;
    const int tq1 = tq0 + 8;
    const int tqmin = q0 + warp * 16;
    const int tqmax = tqmin + 15;

    float mrun0 = -INFINITY, mrun1 = -INFINITY;
    float lsum0 = 0.f, lsum1 = 0.f;
    float O[8][4];
#pragma unroll
    for (int j = 0; j < 8; j++)
#pragma unroll
        for (int e = 0; e < 4; e++) O[j][e] = 0.f;

    uint32_t Qa[4][4];

    for (int t = 0; t < ntiles; t++) {
        if (t + 1 < ntiles) { CP_WAIT(1); } else { CP_WAIT(0); }
        __syncthreads();

        if (t + 2 < ntiles) stage_kv(t + 2, (t + 2) % 3);

        if (t == 0) {
            const uint32_t qb = smem_u32(Qs);
#pragma unroll
            for (int ks = 0; ks < 4; ks++) {
                uint32_t addr = qb + ((warp * 16 + (lane & 15)) * AT_STRIDE
                                      + ks * 16 + (lane >> 4) * 8) * 2;
                LDSM_X4(Qa[ks][0], Qa[ks][1], Qa[ks][2], Qa[ks][3], addr);
            }
        }

        const int j0 = kstart + t * 32;
        const int jlast = j0 + 31;

        const bool any_valid = !(j0 > tqmax + w) && !(jlast < tqmin - w)
                               && (j0 <= kend);
        if (!any_valid) continue;
        const bool full_valid = (j0 >= tqmax - w) && (jlast <= tqmin + w)
                                && (jlast <= kend);

        const int p = t % 3;
        const uint32_t kb = smem_u32(Ks[p]);
        const uint32_t vb = smem_u32(Vs[p]);

        float s[4][4];
#pragma unroll
        for (int j = 0; j < 4; j++)
#pragma unroll
            for (int e = 0; e < 4; e++) s[j][e] = 0.f;
#pragma unroll
        for (int ks = 0; ks < 4; ks++) {
#pragma unroll
            for (int jp = 0; jp < 2; jp++) {
                int row = jp * 16 + (lane & 7) + ((lane >> 4) << 3);
                int col = ks * 16 + ((lane >> 3) & 1) * 8;
                uint32_t addr = kb + (row * AT_STRIDE + col) * 2;
                uint32_t b0, b1, b2, b3;
                LDSM_X4(b0, b1, b2, b3, addr);
                mma16816(s[jp * 2 + 0], Qa[ks][0], Qa[ks][1], Qa[ks][2], Qa[ks][3], b0, b1);
                mma16816(s[jp * 2 + 1], Qa[ks][0], Qa[ks][1], Qa[ks][2], Qa[ks][3], b2, b3);
            }
        }

        if (full_valid) {
#pragma unroll
            for (int j = 0; j < 4; j++) {
                s[j][0] *= 0.125f; s[j][1] *= 0.125f;
                s[j][2] *= 0.125f; s[j][3] *= 0.125f;
            }
        } else {
#pragma unroll
            for (int j = 0; j < 4; j++) {
                int keyb = j0 + j * 8 + (lane & 3) * 2;
#pragma unroll
                for (int e = 0; e < 2; e++) {
                    int key = keyb + e;
                    int d0 = tq0 - key; d0 = d0 < 0 ? -d0 : d0;
                    int d1 = tq1 - key; d1 = d1 < 0 ? -d1 : d1;
                    bool kv = (key <= kend);
                    s[j][e]     = (kv && d0 <= w) ? s[j][e] * 0.125f     : -INFINITY;
                    s[j][2 + e] = (kv && d1 <= w) ? s[j][2 + e] * 0.125f : -INFINITY;
                }
            }
        }

        float mt0 = -INFINITY, mt1 = -INFINITY;
#pragma unroll
        for (int j = 0; j < 4; j++) {
            mt0 = fmaxf(mt0, fmaxf(s[j][0], s[j][1]));
            mt1 = fmaxf(mt1, fmaxf(s[j][2], s[j][3]));
        }
        mt0 = fmaxf(mt0, __shfl_xor_sync(0xffffffffu, mt0, 1));
        mt0 = fmaxf(mt0, __shfl_xor_sync(0xffffffffu, mt0, 2));
        mt1 = fmaxf(mt1, __shfl_xor_sync(0xffffffffu, mt1, 1));
        mt1 = fmaxf(mt1, __shfl_xor_sync(0xffffffffu, mt1, 2));

        float mnew0 = fmaxf(mrun0, mt0);
        float mnew1 = fmaxf(mrun1, mt1);
        float ms0 = (mnew0 == -INFINITY) ? 0.f : mnew0;
        float ms1 = (mnew1 == -INFINITY) ? 0.f : mnew1;
        float alpha0 = __expf(mrun0 - ms0);
        float alpha1 = __expf(mrun1 - ms1);
        mrun0 = mnew0; mrun1 = mnew1;

        float ls0 = 0.f, ls1 = 0.f;
#pragma unroll
        for (int j = 0; j < 4; j++) {
            s[j][0] = __expf(s[j][0] - ms0);
            s[j][1] = __expf(s[j][1] - ms0);
            s[j][2] = __expf(s[j][2] - ms1);
            s[j][3] = __expf(s[j][3] - ms1);
            ls0 += s[j][0] + s[j][1];
            ls1 += s[j][2] + s[j][3];
        }
        ls0 += __shfl_xor_sync(0xffffffffu, ls0, 1);
        ls0 += __shfl_xor_sync(0xffffffffu, ls0, 2);
        ls1 += __shfl_xor_sync(0xffffffffu, ls1, 1);
        ls1 += __shfl_xor_sync(0xffffffffu, ls1, 2);
        lsum0 = lsum0 * alpha0 + ls0;
        lsum1 = lsum1 * alpha1 + ls1;

#pragma unroll
        for (int j = 0; j < 8; j++) {
            O[j][0] *= alpha0; O[j][1] *= alpha0;
            O[j][2] *= alpha1; O[j][3] *= alpha1;
        }

        uint32_t aP[2][4];
#pragma unroll
        for (int s2 = 0; s2 < 2; s2++) {
            aP[s2][0] = h2_u32(__floats2half2_rn(s[s2 * 2][0],     s[s2 * 2][1]));
            aP[s2][1] = h2_u32(__floats2half2_rn(s[s2 * 2][2],     s[s2 * 2][3]));
            aP[s2][2] = h2_u32(__floats2half2_rn(s[s2 * 2 + 1][0], s[s2 * 2 + 1][1]));
            aP[s2][3] = h2_u32(__floats2half2_rn(s[s2 * 2 + 1][2], s[s2 * 2 + 1][3]));
        }

#pragma unroll
        for (int s2 = 0; s2 < 2; s2++) {
#pragma unroll
            for (int jp = 0; jp < 4; jp++) {
                int row = s2 * 16 + (lane & 15);
                int col = jp * 16 + ((lane >> 4) << 3);
                uint32_t addr = vb + (row * AT_STRIDE + col) * 2;
                uint32_t b0, b1, b2, b3;
                LDSM_X4T(b0, b1, b2, b3, addr);
                mma16816(O[jp * 2 + 0], aP[s2][0], aP[s2][1], aP[s2][2], aP[s2][3], b0, b1);
                mma16816(O[jp * 2 + 1], aP[s2][0], aP[s2][1], aP[s2][2], aP[s2][3], b2, b3);
            }
        }
    }

    float inv0 = 1.0f / lsum0;
    float inv1 = 1.0f / lsum1;
    const int coff = hh * 64 + (lane & 3) * 2;
    if (tq0 < TT) {
        __half* op = out + (size_t)(b * TT + tq0) * DMODEL + coff;
#pragma unroll
        for (int j = 0; j < 8; j++)
            *(__half2*)(op + j * 8) = __floats2half2_rn(O[j][0] * inv0, O[j][1] * inv0);
    }
    if (tq1 < TT) {
        __half* op = out + (size_t)(b * TT + tq1) * DMODEL + coff;
#pragma unroll
        for (int j = 0; j < 8; j++)
            *(__half2*)(op + j * 8) = __floats2half2_rn(O[j][2] * inv1, O[j][3] * inv1);
    }
}

// ---------------- residual + LayerNorm (fp16 in/out, fp32 math) -----------
__global__ __launch_bounds__(256)
void resln_kernel(__half* __restrict__ h16, const __half* __restrict__ o16,
                  const float* __restrict__ g, const float* __restrict__ be)
{
    const int row = blockIdx.x;
    const int tid = threadIdx.x;
    const size_t base2 = (size_t)row * 256;
    float2 hx = __half22float2(*(const __half2*)((const __half*)h16 + base2 * 2 + tid * 2));
    float2 ox = __half22float2(*(const __half2*)((const __half*)o16 + base2 * 2 + tid * 2));
    float x0 = hx.x + ox.x;
    float x1 = hx.y + ox.y;
    float s  = x0 + x1;
    float sq = x0 * x0 + x1 * x1;

    __shared__ float ss[8], sqs[8];
#pragma unroll
    for (int off = 16; off > 0; off >>= 1) {
        s  += __shfl_down_sync(0xffffffffu, s, off);
        sq += __shfl_down_sync(0xffffffffu, sq, off);
    }
    int wid = tid >> 5, lane = tid & 31;
    if (lane == 0) { ss[wid] = s; sqs[wid] = sq; }
    __syncthreads();
    if (tid == 0) {
        float st = 0.f, sqt = 0.f;
        for (int i = 0; i < 8; i++) { st += ss[i]; sqt += sqs[i]; }
        ss[0] = st; sqs[0] = sqt;
    }
    __syncthreads();
    float mean = ss[0] * (1.0f / 512.0f);
    float var  = sqs[0] * (1.0f / 512.0f) - mean * mean;
    float r = rsqrtf(var + 1e-5f);
    float y0 = (x0 - mean) * r * g[tid * 2]     + be[tid * 2];
    float y1 = (x1 - mean) * r * g[tid * 2 + 1] + be[tid * 2 + 1];
    *(__half2*)((__half*)h16 + base2 * 2 + tid * 2) = __floats2half2_rn(y0, y1);
}

// ---------------- pooling ----------
__global__ __launch_bounds__(512)
void pool_partial_kernel(const __half* __restrict__ h16, float* __restrict__ part)
{
    const int b = blockIdx.x;
    const int c = blockIdx.y;
    const int tid = threadIdx.x;
    const int t0 = c * 125;
    float mx = -INFINITY;
    for (int t = t0; t < t0 + 125; t++)
        mx = fmaxf(mx, __half2float(h16[((size_t)b * TT + t) * DMODEL + tid]));
    part[((size_t)b * 8 + c) * DMODEL + tid] = mx;
}

__global__ __launch_bounds__(512)
void pool_cls_kernel(const float* __restrict__ part, const float* __restrict__ Wcls,
                     const float* __restrict__ bcls, float* __restrict__ out)
{
    const int b = blockIdx.x;
    const int tid = threadIdx.x;
    float mx = -INFINITY;
#pragma unroll
    for (int c = 0; c < 8; c++)
        mx = fmaxf(mx, part[((size_t)b * 8 + c) * DMODEL + tid]);
    __shared__ float sp[DMODEL];
    __shared__ float logits[NCLS];
    sp[tid] = mx;
    __syncthreads();
    if (tid < NCLS) {
        float s = bcls[tid];
        for (int d = 0; d < DMODEL; d++) s += Wcls[tid * DMODEL + d] * sp[d];
        logits[tid] = s;
    }
    __syncthreads();
    if (tid == 0) {
        float m = -INFINITY;
        for (int c = 0; c < NCLS; c++) m = fmaxf(m, logits[c]);
        float se = 0.f;
        for (int c = 0; c < NCLS; c++) se += expf(logits[c] - m);
        float lse = m + logf(se);
        for (int c = 0; c < NCLS; c++) out[b * NCLS + c] = logits[c] - lse;
    }
}

// ---------------- launch ----------------
extern "C" void kernel_launch(void* const* d_in, const int* in_sizes, int n_in,
                              void* d_out, int out_size)
{
    const float* x    = (const float*)d_in[0];
    const float* Wemb = (const float*)d_in[1];
    const float* bemb = (const float*)d_in[2];
    const float* Wqkv = (const float*)d_in[3];
    const float* bqkv = (const float*)d_in[4];
    const float* Wo   = (const float*)d_in[5];
    const float* bo   = (const float*)d_in[6];
    const float* W1   = (const float*)d_in[7];
    const float* b1f  = (const float*)d_in[8];
    const float* W2   = (const float*)d_in[9];
    const float* b2f  = (const float*)d_in[10];
    const float* g1   = (const float*)d_in[11];
    const float* be1  = (const float*)d_in[12];
    const float* g2   = (const float*)d_in[13];
    const float* be2  = (const float*)d_in[14];
    const float* Wcls = (const float*)d_in[15];
    const float* bcls = (const float*)d_in[16];

    float *pool;
    __half *x16, *h16, *o16, *qkv16, *attn16, *ff16, *wemb16, *wqkv16, *wo16, *wf1, *wf2;
    cudaGetSymbolAddress((void**)&pool,  g_pool);
    cudaGetSymbolAddress((void**)&x16,   g_x16);
    cudaGetSymbolAddress((void**)&h16,   g_h16);
    cudaGetSymbolAddress((void**)&o16,   g_o16);
    cudaGetSymbolAddress((void**)&qkv16, g_qkv16);
    cudaGetSymbolAddress((void**)&attn16,g_attn16);
    cudaGetSymbolAddress((void**)&ff16,  g_ff16);
    cudaGetSymbolAddress((void**)&wemb16,g_w16emb);
    cudaGetSymbolAddress((void**)&wqkv16,g_w16qkv);
    cudaGetSymbolAddress((void**)&wo16,  g_w16o);
    cudaGetSymbolAddress((void**)&wf1,   g_w16f1);
    cudaGetSymbolAddress((void**)&wf2,   g_w16f2);

    cudaFuncSetAttribute(hgemm_kernel,
                         cudaFuncAttributeMaxDynamicSharedMemorySize, HG_SMEM);

    const int GM = (MROWS + 127) / 128;  // 63

    // Launch order: attention(l=0) is launch #4 -> profiled by ncu.
    {
        int n0 = MROWS * INDIM;
        int n1 = DMODEL * INDIM;
        int n2 = NLAYER * 3 * DMODEL * DMODEL;
        int tot = n0 + n1 + n2;
        cvt3_kernel<<<(tot / 4 + 255) / 256, 256>>>(x, x16, n0, Wemb, wemb16, n1,
                                                    Wqkv, wqkv16, n2);
    }
    hgemm_kernel<<<dim3(GM, DMODEL / 128), 256, HG_SMEM>>>(
        x16, wemb16, bemb, h16, MROWS, DMODEL, INDIM, 2);
    hgemm_kernel<<<dim3(GM, (3 * DMODEL) / 128), 256, HG_SMEM>>>(
        h16, wqkv16, bqkv, qkv16, MROWS, 3 * DMODEL, DMODEL, 0);
    attn_mma_kernel<<<dim3(8, NHEAD, BSZ), 256>>>(qkv16, attn16);
    {
        int n0 = NLAYER * DMODEL * DMODEL;
        int n1 = NLAYER * FFDIM * DMODEL;
        int n2 = NLAYER * DMODEL * FFDIM;
        int tot = n0 + n1 + n2;
        cvt3_kernel<<<(tot / 4 + 255) / 256, 256>>>(Wo, wo16, n0, W1, wf1, n1, W2, wf2, n2);
    }

    for (int l = 0; l < NLAYER; l++) {
        if (l > 0) {
            hgemm_kernel<<<dim3(GM, (3 * DMODEL) / 128), 256, HG_SMEM>>>(
                h16, wqkv16 + (size_t)l * 3 * DMODEL * DMODEL,
                bqkv + (size_t)l * 3 * DMODEL, qkv16, MROWS, 3 * DMODEL, DMODEL, 0);
            attn_mma_kernel<<<dim3(8, NHEAD, BSZ), 256>>>(qkv16, attn16);
        }

        hgemm_kernel<<<dim3(GM, DMODEL / 128), 256, HG_SMEM>>>(
            attn16, wo16 + (size_t)l * DMODEL * DMODEL,
            bo + (size_t)l * DMODEL, o16, MROWS, DMODEL, DMODEL, 0);

        resln_kernel<<<MROWS, 256>>>(h16, o16, g1 + (size_t)l * DMODEL,
                                     be1 + (size_t)l * DMODEL);

        hgemm_kernel<<<dim3(GM, FFDIM / 128), 256, HG_SMEM>>>(
            h16, wf1 + (size_t)l * FFDIM * DMODEL,
            b1f + (size_t)l * FFDIM, ff16, MROWS, FFDIM, DMODEL, 1);

        hgemm_kernel<<<dim3(GM, DMODEL / 128), 256, HG_SMEM>>>(
            ff16, wf2 + (size_t)l * DMODEL * FFDIM,
            b2f + (size_t)l * DMODEL, o16, MROWS, DMODEL, FFDIM, 0);

        resln_kernel<<<MROWS, 256>>>(h16, o16, g2 + (size_t)l * DMODEL,
                                     be2 + (size_t)l * DMODEL);
    }

    pool_partial_kernel<<<dim3(BSZ, 8), 512>>>(h16, pool);
    pool_cls_kernel<<<BSZ, 512>>>(pool, Wcls, bcls, (float*)d_out);
}

// round 15
// speedup vs baseline: 1.5099x; 1.5099x over previous
#include <cuda_runtime.h>
#include <cuda_fp16.h>
#include <math.h>
#include <stdint.h>

#define BSZ    8
#define TT     1000
#define INDIM  256
#define DMODEL 512
#define FFDIM  2048
#define NLAYER 4
#define NHEAD  8
#define DHEAD  64
#define NCLS   8
#define MROWS  (BSZ*TT)   /* 8000 */

// ---------------- scratch (no cudaMalloc allowed) ----------------
__device__ float  g_pool[BSZ * 8 * DMODEL];

__device__ __half g_x16   [MROWS * INDIM];
__device__ __half g_h16   [MROWS * DMODEL];
__device__ __half g_o16   [MROWS * DMODEL];
__device__ __half g_qkv16 [MROWS * 3 * DMODEL];
__device__ __half g_attn16[MROWS * DMODEL];
__device__ __half g_ff16  [MROWS * FFDIM];

__device__ __half g_w16emb[DMODEL * INDIM];
__device__ __half g_w16qkv[NLAYER * 3 * DMODEL * DMODEL];
__device__ __half g_w16o  [NLAYER * DMODEL * DMODEL];
__device__ __half g_w16f1 [NLAYER * FFDIM * DMODEL];
__device__ __half g_w16f2 [NLAYER * DMODEL * FFDIM];

// ======================= helpers =======================
__device__ __forceinline__ uint32_t smem_u32(const void* p) {
    return (uint32_t)__cvta_generic_to_shared(p);
}
__device__ __forceinline__ uint32_t h2_u32(__half2 v) {
    return *reinterpret_cast<uint32_t*>(&v);
}
#define CP_ASYNC16(dst, src, pb) \
    asm volatile("cp.async.cg.shared.global [%0], [%1], 16, %2;\n" \
                 :: "r"(dst), "l"(src), "r"(pb))
#define CP_COMMIT() asm volatile("cp.async.commit_group;\n" ::: "memory")
#define CP_WAIT(n)  asm volatile("cp.async.wait_group %0;\n" :: "n"(n) : "memory")

#define LDSM_X4(r0,r1,r2,r3,addr) \
    asm volatile("ldmatrix.sync.aligned.m8n8.x4.shared.b16 {%0,%1,%2,%3}, [%4];" \
                 : "=r"(r0),"=r"(r1),"=r"(r2),"=r"(r3) : "r"(addr))
#define LDSM_X4T(r0,r1,r2,r3,addr) \
    asm volatile("ldmatrix.sync.aligned.m8n8.x4.trans.shared.b16 {%0,%1,%2,%3}, [%4];" \
                 : "=r"(r0),"=r"(r1),"=r"(r2),"=r"(r3) : "r"(addr))

__device__ __forceinline__ void mma16816(float c[4], uint32_t a0, uint32_t a1,
                                         uint32_t a2, uint32_t a3,
                                         uint32_t b0, uint32_t b1) {
    asm volatile(
        "mma.sync.aligned.m16n8k16.row.col.f32.f16.f16.f32 "
        "{%0,%1,%2,%3}, {%4,%5,%6,%7}, {%8,%9}, {%0,%1,%2,%3};"
        : "+f"(c[0]), "+f"(c[1]), "+f"(c[2]), "+f"(c[3])
        : "r"(a0), "r"(a1), "r"(a2), "r"(a3), "r"(b0), "r"(b1));
}

// ======================= fp16 HMMA GEMM =======================
// flags: 1 = relu, 2 = add sinusoidal PE (embedding). Output always fp16.
// K=64 per stage, 3 stages, prefetch distance 2, single __syncthreads/stage.
#define ROWB 144
#define STAGE_BYTES (128 * ROWB)          /* 18432 */
#define HG_SMEM (6 * STAGE_BYTES)         /* 110592 */

__global__ __launch_bounds__(256, 2)
void hgemm_kernel(const __half* __restrict__ A, const __half* __restrict__ W,
                  const float* __restrict__ bias, __half* __restrict__ Ch,
                  int M, int N, int K, int flags)
{
    extern __shared__ char smem[];
    const uint32_t sA = smem_u32(smem);
    const uint32_t sB = sA + 3 * STAGE_BYTES;

    const int tid  = threadIdx.x;
    const int wid  = tid >> 5;
    const int lane = tid & 31;
    const int wm = wid >> 2;
    const int wn = wid & 3;
    const int g   = lane >> 2;
    const int tig = lane & 3;
    const int m0 = blockIdx.x * 128;
    const int n0 = blockIdx.y * 128;

    const int nt = K >> 6;

    auto load_tile = [&](int t, int s) {
        const uint32_t da = sA + s * STAGE_BYTES;
        const uint32_t db = sB + s * STAGE_BYTES;
        const __half* Ak = A + t * 64;
        const __half* Wk = W + t * 64;
#pragma unroll
        for (int it = 0; it < 4; it++) {
            int id  = tid + it * 256;
            int row = id >> 3;
            int c   = id & 7;
            int ar = m0 + row; int arc = ar < M ? ar : (M - 1);
            int pa = (ar < M) ? 16 : 0;
            CP_ASYNC16(da + row * ROWB + c * 16,
                       (const char*)(Ak + (size_t)arc * K) + c * 16, pa);
            CP_ASYNC16(db + row * ROWB + c * 16,
                       (const char*)(Wk + (size_t)(n0 + row) * K) + c * 16, 16);
        }
        CP_COMMIT();
    };

    float acc[4][4][4];
#pragma unroll
    for (int i = 0; i < 4; i++)
#pragma unroll
        for (int j = 0; j < 4; j++)
#pragma unroll
            for (int r = 0; r < 4; r++) acc[i][j][r] = 0.f;

    load_tile(0, 0);
    load_tile(1, 1);

    const int a_row = (lane & 15);
    const int a_col = (lane >> 4) * 8;
    const int b_row = (lane & 7) + ((lane >> 4) << 3);
    const int b_col = ((lane >> 3) & 1) * 8;

    for (int kt = 0; kt < nt; kt++) {
        if (kt + 1 < nt) { CP_WAIT(1); } else { CP_WAIT(0); }
        __syncthreads();   // slot (kt+2)%3 free: its reader was iter kt-1

        if (kt + 2 < nt) load_tile(kt + 2, (kt + 2) % 3);

        const int s = kt % 3;
        const uint32_t baseA = sA + s * STAGE_BYTES;
        const uint32_t baseB = sB + s * STAGE_BYTES;

#pragma unroll
        for (int ks = 0; ks < 4; ks++) {
            const int kk = ks * 16;
            uint32_t bf[4][2];
#pragma unroll
            for (int np = 0; np < 2; np++) {
                uint32_t addr = baseB
                    + (uint32_t)(wn * 32 + np * 16 + b_row) * ROWB
                    + (uint32_t)(kk + b_col) * 2;
                uint32_t b0, b1, b2, b3;
                LDSM_X4(b0, b1, b2, b3, addr);
                bf[np * 2 + 0][0] = b0; bf[np * 2 + 0][1] = b1;
                bf[np * 2 + 1][0] = b2; bf[np * 2 + 1][1] = b3;
            }
            uint32_t af[2][4];
            {
                uint32_t addr = baseA
                    + (uint32_t)(wm * 64 + 0 * 16 + a_row) * ROWB
                    + (uint32_t)(kk + a_col) * 2;
                LDSM_X4(af[0][0], af[0][1], af[0][2], af[0][3], addr);
            }
#pragma unroll
            for (int mi = 0; mi < 4; mi++) {
                if (mi < 3) {
                    uint32_t addr = baseA
                        + (uint32_t)(wm * 64 + (mi + 1) * 16 + a_row) * ROWB
                        + (uint32_t)(kk + a_col) * 2;
                    LDSM_X4(af[(mi + 1) & 1][0], af[(mi + 1) & 1][1],
                            af[(mi + 1) & 1][2], af[(mi + 1) & 1][3], addr);
                }
                const uint32_t* a = af[mi & 1];
#pragma unroll
                for (int ni = 0; ni < 4; ni++)
                    mma16816(acc[mi][ni], a[0], a[1], a[2], a[3],
                             bf[ni][0], bf[ni][1]);
            }
        }
    }

    const int relu  = flags & 1;
    const int addpe = flags & 2;
#pragma unroll
    for (int mi = 0; mi < 4; mi++) {
        int gr0 = m0 + wm * 64 + mi * 16 + g;
        int t0r = gr0 % TT, t1r = (gr0 + 8) % TT;
#pragma unroll
        for (int ni = 0; ni < 4; ni++) {
            int gc = n0 + wn * 32 + ni * 8 + 2 * tig;
            float b0 = bias[gc], b1 = bias[gc + 1];
            float v0 = acc[mi][ni][0] + b0;
            float v1 = acc[mi][ni][1] + b1;
            float v2 = acc[mi][ni][2] + b0;
            float v3 = acc[mi][ni][3] + b1;
            if (relu) {
                v0 = fmaxf(v0, 0.f); v1 = fmaxf(v1, 0.f);
                v2 = fmaxf(v2, 0.f); v3 = fmaxf(v3, 0.f);
            }
            if (addpe) {
                float div = expf((float)gc * (-9.210340371976184f / 512.0f));
                float s0, c0, s1, c1;
                sincosf((float)t0r * div, &s0, &c0);
                sincosf((float)t1r * div, &s1, &c1);
                v0 += s0; v1 += c0; v2 += s1; v3 += c1;
            }
            if (gr0 < M)
                *(__half2*)(Ch + (size_t)gr0 * N + gc) = __floats2half2_rn(v0, v1);
            if (gr0 + 8 < M)
                *(__half2*)(Ch + (size_t)(gr0 + 8) * N + gc) = __floats2half2_rn(v2, v3);
        }
    }
}

// ---------------- fused 3-tensor f32 -> f16 convert ----------------
__global__ void cvt3_kernel(const float* __restrict__ s0, __half* __restrict__ d0, int n0,
                            const float* __restrict__ s1, __half* __restrict__ d1, int n1,
                            const float* __restrict__ s2, __half* __restrict__ d2, int n2)
{
    int i = (blockIdx.x * blockDim.x + threadIdx.x) * 4;
    const float* s; __half* d;
    if (i < n0)           { s = s0; d = d0; }
    else if (i < n0 + n1) { s = s1; d = d1; i -= n0; }
    else if (i < n0 + n1 + n2) { s = s2; d = d2; i -= n0 + n1; }
    else return;
    float4 v = *(const float4*)(s + i);
    *(__half2*)(d + i)     = __floats2half2_rn(v.x, v.y);
    *(__half2*)(d + i + 2) = __floats2half2_rn(v.z, v.w);
}

// ================= HMMA banded flash attention (128 q / block) ============
// 3-slot K/V ring, single __syncthreads per tile, per-warp tile skip.
// Heavy heads (large window) scheduled first: hh = 7 - blockIdx.y.
#define AT_STRIDE 72

__global__ __launch_bounds__(256)
void attn_mma_kernel(const __half* __restrict__ qkv, __half* __restrict__ out)
{
    __shared__ __half Qs[128 * AT_STRIDE];
    __shared__ __half Ks[3][32 * AT_STRIDE];
    __shared__ __half Vs[3][32 * AT_STRIDE];

    const int b  = blockIdx.z;
    const int hh = (NHEAD - 1) - blockIdx.y;   // heavy heads first
    const int q0 = blockIdx.x * 128;
    const int tid  = threadIdx.x;
    const int warp = tid >> 5;
    const int lane = tid & 31;
    const int w = 25 * (hh + 1);

    int kstart = q0 - w;       if (kstart < 0) kstart = 0;
    int kend   = q0 + 127 + w; if (kend > TT - 1) kend = TT - 1;
    const int ntiles = (kend - kstart + 32) >> 5;

    const __half* base = qkv + (size_t)(b * TT) * 1536 + hh * 64;

    {
        const uint32_t qdst = smem_u32(Qs);
        for (int i = tid; i < 1024; i += 256) {
            int row = i >> 3, c = i & 7;
            int tq = q0 + row;
            int rc = tq < TT ? tq : (TT - 1);
            int pb = tq < TT ? 16 : 0;
            CP_ASYNC16(qdst + (row * AT_STRIDE + c * 8) * 2,
                       (const char*)(base + (size_t)rc * 1536 + c * 8), pb);
        }
    }
    auto stage_kv = [&](int t, int p) {
        const uint32_t kdst = smem_u32(Ks[p]);
        const uint32_t vdst = smem_u32(Vs[p]);
        const int j0 = kstart + t * 32;
        {
            int i = tid;
            int row = i >> 3, c = i & 7;
            int key = j0 + row;
            int rc = key < TT ? key : (TT - 1);
            int pb = key < TT ? 16 : 0;
            const __half* src = base + (size_t)rc * 1536 + c * 8;
            CP_ASYNC16(kdst + (row * AT_STRIDE + c * 8) * 2, (const char*)(src + 512),  pb);
            CP_ASYNC16(vdst + (row * AT_STRIDE + c * 8) * 2, (const char*)(src + 1024), pb);
        }
        CP_COMMIT();
    };

    stage_kv(0, 0);
    if (ntiles > 1) stage_kv(1, 1);

    const int r0 = lane >> 2;
    const int tq0 = q0 + warp * 16 + r0;
    const int tq1 = tq0 + 8;
    const int tqmin = q0 + warp * 16;
    const int tqmax = tqmin + 15;

    float mrun0 = -INFINITY, mrun1 = -INFINITY;
    float lsum0 = 0.f, lsum1 = 0.f;
    float O[8][4];
#pragma unroll
    for (int j = 0; j < 8; j++)
#pragma unroll
        for (int e = 0; e < 4; e++) O[j][e] = 0.f;

    uint32_t Qa[4][4];

    for (int t = 0; t < ntiles; t++) {
        if (t + 1 < ntiles) { CP_WAIT(1); } else { CP_WAIT(0); }
        __syncthreads();

        if (t + 2 < ntiles) stage_kv(t + 2, (t + 2) % 3);

        if (t == 0) {
            const uint32_t qb = smem_u32(Qs);
#pragma unroll
            for (int ks = 0; ks < 4; ks++) {
                uint32_t addr = qb + ((warp * 16 + (lane & 15)) * AT_STRIDE
                                      + ks * 16 + (lane >> 4) * 8) * 2;
                LDSM_X4(Qa[ks][0], Qa[ks][1], Qa[ks][2], Qa[ks][3], addr);
            }
        }

        const int j0 = kstart + t * 32;
        const int jlast = j0 + 31;

        const bool any_valid = !(j0 > tqmax + w) && !(jlast < tqmin - w)
                               && (j0 <= kend);
        if (!any_valid) continue;
        const bool full_valid = (j0 >= tqmax - w) && (jlast <= tqmin + w)
                                && (jlast <= kend);

        const int p = t % 3;
        const uint32_t kb = smem_u32(Ks[p]);
        const uint32_t vb = smem_u32(Vs[p]);

        float s[4][4];
#pragma unroll
        for (int j = 0; j < 4; j++)
#pragma unroll
            for (int e = 0; e < 4; e++) s[j][e] = 0.f;
#pragma unroll
        for (int ks = 0; ks < 4; ks++) {
#pragma unroll
            for (int jp = 0; jp < 2; jp++) {
                int row = jp * 16 + (lane & 7) + ((lane >> 4) << 3);
                int col = ks * 16 + ((lane >> 3) & 1) * 8;
                uint32_t addr = kb + (row * AT_STRIDE + col) * 2;
                uint32_t b0, b1, b2, b3;
                LDSM_X4(b0, b1, b2, b3, addr);
                mma16816(s[jp * 2 + 0], Qa[ks][0], Qa[ks][1], Qa[ks][2], Qa[ks][3], b0, b1);
                mma16816(s[jp * 2 + 1], Qa[ks][0], Qa[ks][1], Qa[ks][2], Qa[ks][3], b2, b3);
            }
        }

        if (full_valid) {
#pragma unroll
            for (int j = 0; j < 4; j++) {
                s[j][0] *= 0.125f; s[j][1] *= 0.125f;
                s[j][2] *= 0.125f; s[j][3] *= 0.125f;
            }
        } else {
#pragma unroll
            for (int j = 0; j < 4; j++) {
                int keyb = j0 + j * 8 + (lane & 3) * 2;
#pragma unroll
                for (int e = 0; e < 2; e++) {
                    int key = keyb + e;
                    int d0 = tq0 - key; d0 = d0 < 0 ? -d0 : d0;
                    int d1 = tq1 - key; d1 = d1 < 0 ? -d1 : d1;
                    bool kv = (key <= kend);
                    s[j][e]     = (kv && d0 <= w) ? s[j][e] * 0.125f     : -INFINITY;
                    s[j][2 + e] = (kv && d1 <= w) ? s[j][2 + e] * 0.125f : -INFINITY;
                }
            }
        }

        float mt0 = -INFINITY, mt1 = -INFINITY;
#pragma unroll
        for (int j = 0; j < 4; j++) {
            mt0 = fmaxf(mt0, fmaxf(s[j][0], s[j][1]));
            mt1 = fmaxf(mt1, fmaxf(s[j][2], s[j][3]));
        }
        mt0 = fmaxf(mt0, __shfl_xor_sync(0xffffffffu, mt0, 1));
        mt0 = fmaxf(mt0, __shfl_xor_sync(0xffffffffu, mt0, 2));
        mt1 = fmaxf(mt1, __shfl_xor_sync(0xffffffffu, mt1, 1));
        mt1 = fmaxf(mt1, __shfl_xor_sync(0xffffffffu, mt1, 2));

        float mnew0 = fmaxf(mrun0, mt0);
        float mnew1 = fmaxf(mrun1, mt1);
        float ms0 = (mnew0 == -INFINITY) ? 0.f : mnew0;
        float ms1 = (mnew1 == -INFINITY) ? 0.f : mnew1;
        float alpha0 = __expf(mrun0 - ms0);
        float alpha1 = __expf(mrun1 - ms1);
        mrun0 = mnew0; mrun1 = mnew1;

        float ls0 = 0.f, ls1 = 0.f;
#pragma unroll
        for (int j = 0; j < 4; j++) {
            s[j][0] = __expf(s[j][0] - ms0);
            s[j][1] = __expf(s[j][1] - ms0);
            s[j][2] = __expf(s[j][2] - ms1);
            s[j][3] = __expf(s[j][3] - ms1);
            ls0 += s[j][0] + s[j][1];
            ls1 += s[j][2] + s[j][3];
        }
        ls0 += __shfl_xor_sync(0xffffffffu, ls0, 1);
        ls0 += __shfl_xor_sync(0xffffffffu, ls0, 2);
        ls1 += __shfl_xor_sync(0xffffffffu, ls1, 1);
        ls1 += __shfl_xor_sync(0xffffffffu, ls1, 2);
        lsum0 = lsum0 * alpha0 + ls0;
        lsum1 = lsum1 * alpha1 + ls1;

#pragma unroll
        for (int j = 0; j < 8; j++) {
            O[j][0] *= alpha0; O[j][1] *= alpha0;
            O[j][2] *= alpha1; O[j][3] *= alpha1;
        }

        uint32_t aP[2][4];
#pragma unroll
        for (int s2 = 0; s2 < 2; s2++) {
            aP[s2][0] = h2_u32(__floats2half2_rn(s[s2 * 2][0],     s[s2 * 2][1]));
            aP[s2][1] = h2_u32(__floats2half2_rn(s[s2 * 2][2],     s[s2 * 2][3]));
            aP[s2][2] = h2_u32(__floats2half2_rn(s[s2 * 2 + 1][0], s[s2 * 2 + 1][1]));
            aP[s2][3] = h2_u32(__floats2half2_rn(s[s2 * 2 + 1][2], s[s2 * 2 + 1][3]));
        }

#pragma unroll
        for (int s2 = 0; s2 < 2; s2++) {
#pragma unroll
            for (int jp = 0; jp < 4; jp++) {
                int row = s2 * 16 + (lane & 15);
                int col = jp * 16 + ((lane >> 4) << 3);
                uint32_t addr = vb + (row * AT_STRIDE + col) * 2;
                uint32_t b0, b1, b2, b3;
                LDSM_X4T(b0, b1, b2, b3, addr);
                mma16816(O[jp * 2 + 0], aP[s2][0], aP[s2][1], aP[s2][2], aP[s2][3], b0, b1);
                mma16816(O[jp * 2 + 1], aP[s2][0], aP[s2][1], aP[s2][2], aP[s2][3], b2, b3);
            }
        }
    }

    float inv0 = 1.0f / lsum0;
    float inv1 = 1.0f / lsum1;
    const int coff = hh * 64 + (lane & 3) * 2;
    if (tq0 < TT) {
        __half* op = out + (size_t)(b * TT + tq0) * DMODEL + coff;
#pragma unroll
        for (int j = 0; j < 8; j++)
            *(__half2*)(op + j * 8) = __floats2half2_rn(O[j][0] * inv0, O[j][1] * inv0);
    }
    if (tq1 < TT) {
        __half* op = out + (size_t)(b * TT + tq1) * DMODEL + coff;
#pragma unroll
        for (int j = 0; j < 8; j++)
            *(__half2*)(op + j * 8) = __floats2half2_rn(O[j][2] * inv1, O[j][3] * inv1);
    }
}

// ---------------- residual + LayerNorm (fp16 in/out, fp32 math) -----------
__global__ __launch_bounds__(256)
void resln_kernel(__half* __restrict__ h16, const __half* __restrict__ o16,
                  const float* __restrict__ g, const float* __restrict__ be)
{
    const int row = blockIdx.x;
    const int tid = threadIdx.x;
    const size_t base2 = (size_t)row * 256;
    float2 hx = __half22float2(*(const __half2*)((const __half*)h16 + base2 * 2 + tid * 2));
    float2 ox = __half22float2(*(const __half2*)((const __half*)o16 + base2 * 2 + tid * 2));
    float x0 = hx.x + ox.x;
    float x1 = hx.y + ox.y;
    float s  = x0 + x1;
    float sq = x0 * x0 + x1 * x1;

    __shared__ float ss[8], sqs[8];
#pragma unroll
    for (int off = 16; off > 0; off >>= 1) {
        s  += __shfl_down_sync(0xffffffffu, s, off);
        sq += __shfl_down_sync(0xffffffffu, sq, off);
    }
    int wid = tid >> 5, lane = tid & 31;
    if (lane == 0) { ss[wid] = s; sqs[wid] = sq; }
    __syncthreads();
    if (tid == 0) {
        float st = 0.f, sqt = 0.f;
        for (int i = 0; i < 8; i++) { st += ss[i]; sqt += sqs[i]; }
        ss[0] = st; sqs[0] = sqt;
    }
    __syncthreads();
    float mean = ss[0] * (1.0f / 512.0f);
    float var  = sqs[0] * (1.0f / 512.0f) - mean * mean;
    float r = rsqrtf(var + 1e-5f);
    float y0 = (x0 - mean) * r * g[tid * 2]     + be[tid * 2];
    float y1 = (x1 - mean) * r * g[tid * 2 + 1] + be[tid * 2 + 1];
    *(__half2*)((__half*)h16 + base2 * 2 + tid * 2) = __floats2half2_rn(y0, y1);
}

// ---------------- pooling ----------
__global__ __launch_bounds__(512)
void pool_partial_kernel(const __half* __restrict__ h16, float* __restrict__ part)
{
    const int b = blockIdx.x;
    const int c = blockIdx.y;
    const int tid = threadIdx.x;
    const int t0 = c * 125;
    float mx = -INFINITY;
    for (int t = t0; t < t0 + 125; t++)
        mx = fmaxf(mx, __half2float(h16[((size_t)b * TT + t) * DMODEL + tid]));
    part[((size_t)b * 8 + c) * DMODEL + tid] = mx;
}

__global__ __launch_bounds__(512)
void pool_cls_kernel(const float* __restrict__ part, const float* __restrict__ Wcls,
                     const float* __restrict__ bcls, float* __restrict__ out)
{
    const int b = blockIdx.x;
    const int tid = threadIdx.x;
    float mx = -INFINITY;
#pragma unroll
    for (int c = 0; c < 8; c++)
        mx = fmaxf(mx, part[((size_t)b * 8 + c) * DMODEL + tid]);
    __shared__ float sp[DMODEL];
    __shared__ float logits[NCLS];
    sp[tid] = mx;
    __syncthreads();
    if (tid < NCLS) {
        float s = bcls[tid];
        for (int d = 0; d < DMODEL; d++) s += Wcls[tid * DMODEL + d] * sp[d];
        logits[tid] = s;
    }
    __syncthreads();
    if (tid == 0) {
        float m = -INFINITY;
        for (int c = 0; c < NCLS; c++) m = fmaxf(m, logits[c]);
        float se = 0.f;
        for (int c = 0; c < NCLS; c++) se += expf(logits[c] - m);
        float lse = m + logf(se);
        for (int c = 0; c < NCLS; c++) out[b * NCLS + c] = logits[c] - lse;
    }
}

// ---------------- launch ----------------
extern "C" void kernel_launch(void* const* d_in, const int* in_sizes, int n_in,
                              void* d_out, int out_size)
{
    const float* x    = (const float*)d_in[0];
    const float* Wemb = (const float*)d_in[1];
    const float* bemb = (const float*)d_in[2];
    const float* Wqkv = (const float*)d_in[3];
    const float* bqkv = (const float*)d_in[4];
    const float* Wo   = (const float*)d_in[5];
    const float* bo   = (const float*)d_in[6];
    const float* W1   = (const float*)d_in[7];
    const float* b1f  = (const float*)d_in[8];
    const float* W2   = (const float*)d_in[9];
    const float* b2f  = (const float*)d_in[10];
    const float* g1   = (const float*)d_in[11];
    const float* be1  = (const float*)d_in[12];
    const float* g2   = (const float*)d_in[13];
    const float* be2  = (const float*)d_in[14];
    const float* Wcls = (const float*)d_in[15];
    const float* bcls = (const float*)d_in[16];

    float *pool;
    __half *x16, *h16, *o16, *qkv16, *attn16, *ff16, *wemb16, *wqkv16, *wo16, *wf1, *wf2;
    cudaGetSymbolAddress((void**)&pool,  g_pool);
    cudaGetSymbolAddress((void**)&x16,   g_x16);
    cudaGetSymbolAddress((void**)&h16,   g_h16);
    cudaGetSymbolAddress((void**)&o16,   g_o16);
    cudaGetSymbolAddress((void**)&qkv16, g_qkv16);
    cudaGetSymbolAddress((void**)&attn16,g_attn16);
    cudaGetSymbolAddress((void**)&ff16,  g_ff16);
    cudaGetSymbolAddress((void**)&wemb16,g_w16emb);
    cudaGetSymbolAddress((void**)&wqkv16,g_w16qkv);
    cudaGetSymbolAddress((void**)&wo16,  g_w16o);
    cudaGetSymbolAddress((void**)&wf1,   g_w16f1);
    cudaGetSymbolAddress((void**)&wf2,   g_w16f2);

    cudaFuncSetAttribute(hgemm_kernel,
                         cudaFuncAttributeMaxDynamicSharedMemorySize, HG_SMEM);

    const int GM = (MROWS + 127) / 128;  // 63

    // Launch order: attention(l=0) is launch #4 -> profiled by ncu.
    {
        int n0 = MROWS * INDIM;
        int n1 = DMODEL * INDIM;
        int n2 = NLAYER * 3 * DMODEL * DMODEL;
        int tot = n0 + n1 + n2;
        cvt3_kernel<<<(tot / 4 + 255) / 256, 256>>>(x, x16, n0, Wemb, wemb16, n1,
                                                    Wqkv, wqkv16, n2);
    }
    hgemm_kernel<<<dim3(GM, DMODEL / 128), 256, HG_SMEM>>>(
        x16, wemb16, bemb, h16, MROWS, DMODEL, INDIM, 2);
    hgemm_kernel<<<dim3(GM, (3 * DMODEL) / 128), 256, HG_SMEM>>>(
        h16, wqkv16, bqkv, qkv16, MROWS, 3 * DMODEL, DMODEL, 0);
    attn_mma_kernel<<<dim3(8, NHEAD, BSZ), 256>>>(qkv16, attn16);
    {
        int n0 = NLAYER * DMODEL * DMODEL;
        int n1 = NLAYER * FFDIM * DMODEL;
        int n2 = NLAYER * DMODEL * FFDIM;
        int tot = n0 + n1 + n2;
        cvt3_kernel<<<(tot / 4 + 255) / 256, 256>>>(Wo, wo16, n0, W1, wf1, n1, W2, wf2, n2);
    }

    for (int l = 0; l < NLAYER; l++) {
        if (l > 0) {
            hgemm_kernel<<<dim3(GM, (3 * DMODEL) / 128), 256, HG_SMEM>>>(
                h16, wqkv16 + (size_t)l * 3 * DMODEL * DMODEL,
                bqkv + (size_t)l * 3 * DMODEL, qkv16, MROWS, 3 * DMODEL, DMODEL, 0);
            attn_mma_kernel<<<dim3(8, NHEAD, BSZ), 256>>>(qkv16, attn16);
        }

        hgemm_kernel<<<dim3(GM, DMODEL / 128), 256, HG_SMEM>>>(
            attn16, wo16 + (size_t)l * DMODEL * DMODEL,
            bo + (size_t)l * DMODEL, o16, MROWS, DMODEL, DMODEL, 0);

        resln_kernel<<<MROWS, 256>>>(h16, o16, g1 + (size_t)l * DMODEL,
                                     be1 + (size_t)l * DMODEL);

        hgemm_kernel<<<dim3(GM, FFDIM / 128), 256, HG_SMEM>>>(
            h16, wf1 + (size_t)l * FFDIM * DMODEL,
            b1f + (size_t)l * FFDIM, ff16, MROWS, FFDIM, DMODEL, 1);

        hgemm_kernel<<<dim3(GM, DMODEL / 128), 256, HG_SMEM>>>(
            ff16, wf2 + (size_t)l * DMODEL * FFDIM,
            b2f + (size_t)l * DMODEL, o16, MROWS, DMODEL, FFDIM, 0);

        resln_kernel<<<MROWS, 256>>>(h16, o16, g2 + (size_t)l * DMODEL,
                                     be2 + (size_t)l * DMODEL);
    }

    pool_partial_kernel<<<dim3(BSZ, 8), 512>>>(h16, pool);
    pool_cls_kernel<<<BSZ, 512>>>(pool, Wcls, bcls, (float*)d_out);
}

// round 16
// speedup vs baseline: 1.5461x; 1.0240x over previous
#include <cuda_runtime.h>
#include <cuda_fp16.h>
#include <math.h>
#include <stdint.h>

#define BSZ    8
#define TT     1000
#define INDIM  256
#define DMODEL 512
#define FFDIM  2048
#define NLAYER 4
#define NHEAD  8
#define DHEAD  64
#define NCLS   8
#define MROWS  (BSZ*TT)   /* 8000 */

// ---------------- scratch (no cudaMalloc allowed) ----------------
__device__ float  g_pool[BSZ * 8 * DMODEL];

__device__ __half g_x16   [MROWS * INDIM];
__device__ __half g_h16   [MROWS * DMODEL];
__device__ __half g_o16   [MROWS * DMODEL];
__device__ __half g_qkv16 [MROWS * 3 * DMODEL];
__device__ __half g_attn16[MROWS * DMODEL];
__device__ __half g_ff16  [MROWS * FFDIM];

__device__ __half g_w16emb[DMODEL * INDIM];
__device__ __half g_w16qkv[NLAYER * 3 * DMODEL * DMODEL];
__device__ __half g_w16o  [NLAYER * DMODEL * DMODEL];
__device__ __half g_w16f1 [NLAYER * FFDIM * DMODEL];
__device__ __half g_w16f2 [NLAYER * DMODEL * FFDIM];

// ======================= helpers =======================
__device__ __forceinline__ uint32_t smem_u32(const void* p) {
    return (uint32_t)__cvta_generic_to_shared(p);
}
__device__ __forceinline__ uint32_t h2_u32(__half2 v) {
    return *reinterpret_cast<uint32_t*>(&v);
}
#define CP_ASYNC16(dst, src, pb) \
    asm volatile("cp.async.cg.shared.global [%0], [%1], 16, %2;\n" \
                 :: "r"(dst), "l"(src), "r"(pb))
#define CP_COMMIT() asm volatile("cp.async.commit_group;\n" ::: "memory")
#define CP_WAIT(n)  asm volatile("cp.async.wait_group %0;\n" :: "n"(n) : "memory")

#define LDSM_X4(r0,r1,r2,r3,addr) \
    asm volatile("ldmatrix.sync.aligned.m8n8.x4.shared.b16 {%0,%1,%2,%3}, [%4];" \
                 : "=r"(r0),"=r"(r1),"=r"(r2),"=r"(r3) : "r"(addr))
#define LDSM_X4T(r0,r1,r2,r3,addr) \
    asm volatile("ldmatrix.sync.aligned.m8n8.x4.trans.shared.b16 {%0,%1,%2,%3}, [%4];" \
                 : "=r"(r0),"=r"(r1),"=r"(r2),"=r"(r3) : "r"(addr))

__device__ __forceinline__ void mma16816(float c[4], uint32_t a0, uint32_t a1,
                                         uint32_t a2, uint32_t a3,
                                         uint32_t b0, uint32_t b1) {
    asm volatile(
        "mma.sync.aligned.m16n8k16.row.col.f32.f16.f16.f32 "
        "{%0,%1,%2,%3}, {%4,%5,%6,%7}, {%8,%9}, {%0,%1,%2,%3};"
        : "+f"(c[0]), "+f"(c[1]), "+f"(c[2]), "+f"(c[3])
        : "r"(a0), "r"(a1), "r"(a2), "r"(a3), "r"(b0), "r"(b1));
}

// ======================= fp16 HMMA GEMM =======================
// flags: 1 = relu, 2 = add sinusoidal PE (embedding). Output always fp16.
// K=64 per stage, 3 stages, prefetch distance 2, single __syncthreads/stage.
#define ROWB 144
#define STAGE_BYTES (128 * ROWB)          /* 18432 */
#define HG_SMEM (6 * STAGE_BYTES)         /* 110592 */

__global__ __launch_bounds__(256, 2)
void hgemm_kernel(const __half* __restrict__ A, const __half* __restrict__ W,
                  const float* __restrict__ bias, __half* __restrict__ Ch,
                  int M, int N, int K, int flags)
{
    extern __shared__ char smem[];
    const uint32_t sA = smem_u32(smem);
    const uint32_t sB = sA + 3 * STAGE_BYTES;

    const int tid  = threadIdx.x;
    const int wid  = tid >> 5;
    const int lane = tid & 31;
    const int wm = wid >> 2;
    const int wn = wid & 3;
    const int g   = lane >> 2;
    const int tig = lane & 3;
    const int m0 = blockIdx.x * 128;
    const int n0 = blockIdx.y * 128;

    const int nt = K >> 6;

    auto load_tile = [&](int t, int s) {
        const uint32_t da = sA + s * STAGE_BYTES;
        const uint32_t db = sB + s * STAGE_BYTES;
        const __half* Ak = A + t * 64;
        const __half* Wk = W + t * 64;
#pragma unroll
        for (int it = 0; it < 4; it++) {
            int id  = tid + it * 256;
            int row = id >> 3;
            int c   = id & 7;
            int ar = m0 + row; int arc = ar < M ? ar : (M - 1);
            int pa = (ar < M) ? 16 : 0;
            CP_ASYNC16(da + row * ROWB + c * 16,
                       (const char*)(Ak + (size_t)arc * K) + c * 16, pa);
            CP_ASYNC16(db + row * ROWB + c * 16,
                       (const char*)(Wk + (size_t)(n0 + row) * K) + c * 16, 16);
        }
        CP_COMMIT();
    };

    float acc[4][4][4];
#pragma unroll
    for (int i = 0; i < 4; i++)
#pragma unroll
        for (int j = 0; j < 4; j++)
#pragma unroll
            for (int r = 0; r < 4; r++) acc[i][j][r] = 0.f;

    load_tile(0, 0);
    load_tile(1, 1);

    const int a_row = (lane & 15);
    const int a_col = (lane >> 4) * 8;
    const int b_row = (lane & 7) + ((lane >> 4) << 3);
    const int b_col = ((lane >> 3) & 1) * 8;

    for (int kt = 0; kt < nt; kt++) {
        if (kt + 1 < nt) { CP_WAIT(1); } else { CP_WAIT(0); }
        __syncthreads();

        if (kt + 2 < nt) load_tile(kt + 2, (kt + 2) % 3);

        const int s = kt % 3;
        const uint32_t baseA = sA + s * STAGE_BYTES;
        const uint32_t baseB = sB + s * STAGE_BYTES;

#pragma unroll
        for (int ks = 0; ks < 4; ks++) {
            const int kk = ks * 16;
            uint32_t bf[4][2];
#pragma unroll
            for (int np = 0; np < 2; np++) {
                uint32_t addr = baseB
                    + (uint32_t)(wn * 32 + np * 16 + b_row) * ROWB
                    + (uint32_t)(kk + b_col) * 2;
                uint32_t b0, b1, b2, b3;
                LDSM_X4(b0, b1, b2, b3, addr);
                bf[np * 2 + 0][0] = b0; bf[np * 2 + 0][1] = b1;
                bf[np * 2 + 1][0] = b2; bf[np * 2 + 1][1] = b3;
            }
            uint32_t af[2][4];
            {
                uint32_t addr = baseA
                    + (uint32_t)(wm * 64 + 0 * 16 + a_row) * ROWB
                    + (uint32_t)(kk + a_col) * 2;
                LDSM_X4(af[0][0], af[0][1], af[0][2], af[0][3], addr);
            }
#pragma unroll
            for (int mi = 0; mi < 4; mi++) {
                if (mi < 3) {
                    uint32_t addr = baseA
                        + (uint32_t)(wm * 64 + (mi + 1) * 16 + a_row) * ROWB
                        + (uint32_t)(kk + a_col) * 2;
                    LDSM_X4(af[(mi + 1) & 1][0], af[(mi + 1) & 1][1],
                            af[(mi + 1) & 1][2], af[(mi + 1) & 1][3], addr);
                }
                const uint32_t* a = af[mi & 1];
#pragma unroll
                for (int ni = 0; ni < 4; ni++)
                    mma16816(acc[mi][ni], a[0], a[1], a[2], a[3],
                             bf[ni][0], bf[ni][1]);
            }
        }
    }

    const int relu  = flags & 1;
    const int addpe = flags & 2;
#pragma unroll
    for (int mi = 0; mi < 4; mi++) {
        int gr0 = m0 + wm * 64 + mi * 16 + g;
        int t0r = gr0 % TT, t1r = (gr0 + 8) % TT;
#pragma unroll
        for (int ni = 0; ni < 4; ni++) {
            int gc = n0 + wn * 32 + ni * 8 + 2 * tig;
            float b0 = bias[gc], b1 = bias[gc + 1];
            float v0 = acc[mi][ni][0] + b0;
            float v1 = acc[mi][ni][1] + b1;
            float v2 = acc[mi][ni][2] + b0;
            float v3 = acc[mi][ni][3] + b1;
            if (relu) {
                v0 = fmaxf(v0, 0.f); v1 = fmaxf(v1, 0.f);
                v2 = fmaxf(v2, 0.f); v3 = fmaxf(v3, 0.f);
            }
            if (addpe) {
                float div = expf((float)gc * (-9.210340371976184f / 512.0f));
                float s0, c0, s1, c1;
                sincosf((float)t0r * div, &s0, &c0);
                sincosf((float)t1r * div, &s1, &c1);
                v0 += s0; v1 += c0; v2 += s1; v3 += c1;
            }
            if (gr0 < M)
                *(__half2*)(Ch + (size_t)gr0 * N + gc) = __floats2half2_rn(v0, v1);
            if (gr0 + 8 < M)
                *(__half2*)(Ch + (size_t)(gr0 + 8) * N + gc) = __floats2half2_rn(v2, v3);
        }
    }
}

// ---------------- fused 3-tensor f32 -> f16 convert ----------------
__global__ void cvt3_kernel(const float* __restrict__ s0, __half* __restrict__ d0, int n0,
                            const float* __restrict__ s1, __half* __restrict__ d1, int n1,
                            const float* __restrict__ s2, __half* __restrict__ d2, int n2)
{
    int i = (blockIdx.x * blockDim.x + threadIdx.x) * 4;
    const float* s; __half* d;
    if (i < n0)           { s = s0; d = d0; }
    else if (i < n0 + n1) { s = s1; d = d1; i -= n0; }
    else if (i < n0 + n1 + n2) { s = s2; d = d2; i -= n0 + n1; }
    else return;
    float4 v = *(const float4*)(s + i);
    *(__half2*)(d + i)     = __floats2half2_rn(v.x, v.y);
    *(__half2*)(d + i + 2) = __floats2half2_rn(v.z, v.w);
}

// ================= HMMA banded flash attention (128 q / block) ============
// 3-slot K/V ring, single __syncthreads per tile, per-warp tile skip.
// min-blocks 3 to force <=85 regs -> 3 CTAs/SM.
#define AT_STRIDE 72

__global__ __launch_bounds__(256, 3)
void attn_mma_kernel(const __half* __restrict__ qkv, __half* __restrict__ out)
{
    __shared__ __half Qs[128 * AT_STRIDE];
    __shared__ __half Ks[3][32 * AT_STRIDE];
    __shared__ __half Vs[3][32 * AT_STRIDE];

    const int b  = blockIdx.z;
    const int hh = (NHEAD - 1) - blockIdx.y;   // heavy heads first
    const int q0 = blockIdx.x * 128;
    const int tid  = threadIdx.x;
    const int warp = tid >> 5;
    const int lane = tid & 31;
    const int w = 25 * (hh + 1);

    int kstart = q0 - w;       if (kstart < 0) kstart = 0;
    int kend   = q0 + 127 + w; if (kend > TT - 1) kend = TT - 1;
    const int ntiles = (kend - kstart + 32) >> 5;

    const __half* base = qkv + (size_t)(b * TT) * 1536 + hh * 64;

    {
        const uint32_t qdst = smem_u32(Qs);
        for (int i = tid; i < 1024; i += 256) {
            int row = i >> 3, c = i & 7;
            int tq = q0 + row;
            int rc = tq < TT ? tq : (TT - 1);
            int pb = tq < TT ? 16 : 0;
            CP_ASYNC16(qdst + (row * AT_STRIDE + c * 8) * 2,
                       (const char*)(base + (size_t)rc * 1536 + c * 8), pb);
        }
    }
    auto stage_kv = [&](int t, int p) {
        const uint32_t kdst = smem_u32(Ks[p]);
        const uint32_t vdst = smem_u32(Vs[p]);
        const int j0 = kstart + t * 32;
        {
            int i = tid;
            int row = i >> 3, c = i & 7;
            int key = j0 + row;
            int rc = key < TT ? key : (TT - 1);
            int pb = key < TT ? 16 : 0;
            const __half* src = base + (size_t)rc * 1536 + c * 8;
            CP_ASYNC16(kdst + (row * AT_STRIDE + c * 8) * 2, (const char*)(src + 512),  pb);
            CP_ASYNC16(vdst + (row * AT_STRIDE + c * 8) * 2, (const char*)(src + 1024), pb);
        }
        CP_COMMIT();
    };

    stage_kv(0, 0);
    if (ntiles > 1) stage_kv(1, 1);

    const int r0 = lane >> 2;
    const int tq0 = q0 + warp * 16 + r0;
    const int tq1 = tq0 + 8;
    const int tqmin = q0 + warp * 16;
    const int tqmax = tqmin + 15;

    float mrun0 = -INFINITY, mrun1 = -INFINITY;
    float lsum0 = 0.f, lsum1 = 0.f;
    float O[8][4];
#pragma unroll
    for (int j = 0; j < 8; j++)
#pragma unroll
        for (int e = 0; e < 4; e++) O[j][e] = 0.f;

    uint32_t Qa[4][4];

    for (int t = 0; t < ntiles; t++) {
        if (t + 1 < ntiles) { CP_WAIT(1); } else { CP_WAIT(0); }
        __syncthreads();

        if (t + 2 < ntiles) stage_kv(t + 2, (t + 2) % 3);

        if (t == 0) {
            const uint32_t qb = smem_u32(Qs);
#pragma unroll
            for (int ks = 0; ks < 4; ks++) {
                uint32_t addr = qb + ((warp * 16 + (lane & 15)) * AT_STRIDE
                                      + ks * 16 + (lane >> 4) * 8) * 2;
                LDSM_X4(Qa[ks][0], Qa[ks][1], Qa[ks][2], Qa[ks][3], addr);
            }
        }

        const int j0 = kstart + t * 32;
        const int jlast = j0 + 31;

        const bool any_valid = !(j0 > tqmax + w) && !(jlast < tqmin - w)
                               && (j0 <= kend);
        if (!any_valid) continue;
        const bool full_valid = (j0 >= tqmax - w) && (jlast <= tqmin + w)
                                && (jlast <= kend);

        const int p = t % 3;
        const uint32_t kb = smem_u32(Ks[p]);
        const uint32_t vb = smem_u32(Vs[p]);

        float s[4][4];
#pragma unroll
        for (int j = 0; j < 4; j++)
#pragma unroll
            for (int e = 0; e < 4; e++) s[j][e] = 0.f;
#pragma unroll
        for (int ks = 0; ks < 4; ks++) {
#pragma unroll
            for (int jp = 0; jp < 2; jp++) {
                int row = jp * 16 + (lane & 7) + ((lane >> 4) << 3);
                int col = ks * 16 + ((lane >> 3) & 1) * 8;
                uint32_t addr = kb + (row * AT_STRIDE + col) * 2;
                uint32_t b0, b1, b2, b3;
                LDSM_X4(b0, b1, b2, b3, addr);
                mma16816(s[jp * 2 + 0], Qa[ks][0], Qa[ks][1], Qa[ks][2], Qa[ks][3], b0, b1);
                mma16816(s[jp * 2 + 1], Qa[ks][0], Qa[ks][1], Qa[ks][2], Qa[ks][3], b2, b3);
            }
        }

        if (full_valid) {
#pragma unroll
            for (int j = 0; j < 4; j++) {
                s[j][0] *= 0.125f; s[j][1] *= 0.125f;
                s[j][2] *= 0.125f; s[j][3] *= 0.125f;
            }
        } else {
#pragma unroll
            for (int j = 0; j < 4; j++) {
                int keyb = j0 + j * 8 + (lane & 3) * 2;
#pragma unroll
                for (int e = 0; e < 2; e++) {
                    int key = keyb + e;
                    int d0 = tq0 - key; d0 = d0 < 0 ? -d0 : d0;
                    int d1 = tq1 - key; d1 = d1 < 0 ? -d1 : d1;
                    bool kv = (key <= kend);
                    s[j][e]     = (kv && d0 <= w) ? s[j][e] * 0.125f     : -INFINITY;
                    s[j][2 + e] = (kv && d1 <= w) ? s[j][2 + e] * 0.125f : -INFINITY;
                }
            }
        }

        float mt0 = -INFINITY, mt1 = -INFINITY;
#pragma unroll
        for (int j = 0; j < 4; j++) {
            mt0 = fmaxf(mt0, fmaxf(s[j][0], s[j][1]));
            mt1 = fmaxf(mt1, fmaxf(s[j][2], s[j][3]));
        }
        mt0 = fmaxf(mt0, __shfl_xor_sync(0xffffffffu, mt0, 1));
        mt0 = fmaxf(mt0, __shfl_xor_sync(0xffffffffu, mt0, 2));
        mt1 = fmaxf(mt1, __shfl_xor_sync(0xffffffffu, mt1, 1));
        mt1 = fmaxf(mt1, __shfl_xor_sync(0xffffffffu, mt1, 2));

        float mnew0 = fmaxf(mrun0, mt0);
        float mnew1 = fmaxf(mrun1, mt1);
        float ms0 = (mnew0 == -INFINITY) ? 0.f : mnew0;
        float ms1 = (mnew1 == -INFINITY) ? 0.f : mnew1;
        float alpha0 = __expf(mrun0 - ms0);
        float alpha1 = __expf(mrun1 - ms1);
        mrun0 = mnew0; mrun1 = mnew1;

        float ls0 = 0.f, ls1 = 0.f;
#pragma unroll
        for (int j = 0; j < 4; j++) {
            s[j][0] = __expf(s[j][0] - ms0);
            s[j][1] = __expf(s[j][1] - ms0);
            s[j][2] = __expf(s[j][2] - ms1);
            s[j][3] = __expf(s[j][3] - ms1);
            ls0 += s[j][0] + s[j][1];
            ls1 += s[j][2] + s[j][3];
        }
        ls0 += __shfl_xor_sync(0xffffffffu, ls0, 1);
        ls0 += __shfl_xor_sync(0xffffffffu, ls0, 2);
        ls1 += __shfl_xor_sync(0xffffffffu, ls1, 1);
        ls1 += __shfl_xor_sync(0xffffffffu, ls1, 2);
        lsum0 = lsum0 * alpha0 + ls0;
        lsum1 = lsum1 * alpha1 + ls1;

#pragma unroll
        for (int j = 0; j < 8; j++) {
            O[j][0] *= alpha0; O[j][1] *= alpha0;
            O[j][2] *= alpha1; O[j][3] *= alpha1;
        }

        uint32_t aP[2][4];
#pragma unroll
        for (int s2 = 0; s2 < 2; s2++) {
            aP[s2][0] = h2_u32(__floats2half2_rn(s[s2 * 2][0],     s[s2 * 2][1]));
            aP[s2][1] = h2_u32(__floats2half2_rn(s[s2 * 2][2],     s[s2 * 2][3]));
            aP[s2][2] = h2_u32(__floats2half2_rn(s[s2 * 2 + 1][0], s[s2 * 2 + 1][1]));
            aP[s2][3] = h2_u32(__floats2half2_rn(s[s2 * 2 + 1][2], s[s2 * 2 + 1][3]));
        }

#pragma unroll
        for (int s2 = 0; s2 < 2; s2++) {
#pragma unroll
            for (int jp = 0; jp < 4; jp++) {
                int row = s2 * 16 + (lane & 15);
                int col = jp * 16 + ((lane >> 4) << 3);
                uint32_t addr = vb + (row * AT_STRIDE + col) * 2;
                uint32_t b0, b1, b2, b3;
                LDSM_X4T(b0, b1, b2, b3, addr);
                mma16816(O[jp * 2 + 0], aP[s2][0], aP[s2][1], aP[s2][2], aP[s2][3], b0, b1);
                mma16816(O[jp * 2 + 1], aP[s2][0], aP[s2][1], aP[s2][2], aP[s2][3], b2, b3);
            }
        }
    }

    float inv0 = 1.0f / lsum0;
    float inv1 = 1.0f / lsum1;
    const int coff = hh * 64 + (lane & 3) * 2;
    if (tq0 < TT) {
        __half* op = out + (size_t)(b * TT + tq0) * DMODEL + coff;
#pragma unroll
        for (int j = 0; j < 8; j++)
            *(__half2*)(op + j * 8) = __floats2half2_rn(O[j][0] * inv0, O[j][1] * inv0);
    }
    if (tq1 < TT) {
        __half* op = out + (size_t)(b * TT + tq1) * DMODEL + coff;
#pragma unroll
        for (int j = 0; j < 8; j++)
            *(__half2*)(op + j * 8) = __floats2half2_rn(O[j][2] * inv1, O[j][3] * inv1);
    }
}

// ------- residual + LayerNorm: one warp per row, warp-local reduce -------
__global__ __launch_bounds__(256)
void resln_kernel(__half* __restrict__ h16, const __half* __restrict__ o16,
                  const float* __restrict__ g, const float* __restrict__ be)
{
    const int row  = blockIdx.x * 8 + (threadIdx.x >> 5);
    const int lane = threadIdx.x & 31;

    const uint4* hp = (const uint4*)(h16 + (size_t)row * DMODEL);
    const uint4* op = (const uint4*)(o16 + (size_t)row * DMODEL);
    uint4 hv[2], ov[2];
    hv[0] = hp[lane]; hv[1] = hp[lane + 32];
    ov[0] = op[lane]; ov[1] = op[lane + 32];

    float x[16];
#pragma unroll
    for (int q = 0; q < 2; q++) {
        const uint32_t* hw = (const uint32_t*)&hv[q];
        const uint32_t* ow = (const uint32_t*)&ov[q];
#pragma unroll
        for (int k = 0; k < 4; k++) {
            __half2 hh2 = *(const __half2*)&hw[k];
            __half2 oo2 = *(const __half2*)&ow[k];
            float2 hf = __half22float2(hh2);
            float2 of = __half22float2(oo2);
            x[q * 8 + k * 2 + 0] = hf.x + of.x;
            x[q * 8 + k * 2 + 1] = hf.y + of.y;
        }
    }

    float s = 0.f, sq = 0.f;
#pragma unroll
    for (int k = 0; k < 16; k++) { s += x[k]; sq += x[k] * x[k]; }
#pragma unroll
    for (int off = 16; off > 0; off >>= 1) {
        s  += __shfl_xor_sync(0xffffffffu, s, off);
        sq += __shfl_xor_sync(0xffffffffu, sq, off);
    }
    float mean = s * (1.0f / 512.0f);
    float var  = sq * (1.0f / 512.0f) - mean * mean;
    float r = rsqrtf(var + 1e-5f);

    uint4* wp = (uint4*)(h16 + (size_t)row * DMODEL);
#pragma unroll
    for (int q = 0; q < 2; q++) {
        int e0 = (q * 32 + lane) * 8;    // element base for this uint4
        float4 g0 = *(const float4*)(g + e0);
        float4 g1 = *(const float4*)(g + e0 + 4);
        float4 b0 = *(const float4*)(be + e0);
        float4 b1 = *(const float4*)(be + e0 + 4);
        uint4 outv;
        uint32_t* owp = (uint32_t*)&outv;
        float y0 = (x[q*8+0] - mean) * r * g0.x + b0.x;
        float y1 = (x[q*8+1] - mean) * r * g0.y + b0.y;
        owp[0] = h2_u32(__floats2half2_rn(y0, y1));
        y0 = (x[q*8+2] - mean) * r * g0.z + b0.z;
        y1 = (x[q*8+3] - mean) * r * g0.w + b0.w;
        owp[1] = h2_u32(__floats2half2_rn(y0, y1));
        y0 = (x[q*8+4] - mean) * r * g1.x + b1.x;
        y1 = (x[q*8+5] - mean) * r * g1.y + b1.y;
        owp[2] = h2_u32(__floats2half2_rn(y0, y1));
        y0 = (x[q*8+6] - mean) * r * g1.z + b1.z;
        y1 = (x[q*8+7] - mean) * r * g1.w + b1.w;
        owp[3] = h2_u32(__floats2half2_rn(y0, y1));
        wp[q * 32 + lane] = outv;
    }
}

// ---------------- pooling ----------
__global__ __launch_bounds__(512)
void pool_partial_kernel(const __half* __restrict__ h16, float* __restrict__ part)
{
    const int b = blockIdx.x;
    const int c = blockIdx.y;
    const int tid = threadIdx.x;
    const int t0 = c * 125;
    float mx = -INFINITY;
    for (int t = t0; t < t0 + 125; t++)
        mx = fmaxf(mx, __half2float(h16[((size_t)b * TT + t) * DMODEL + tid]));
    part[((size_t)b * 8 + c) * DMODEL + tid] = mx;
}

__global__ __launch_bounds__(512)
void pool_cls_kernel(const float* __restrict__ part, const float* __restrict__ Wcls,
                     const float* __restrict__ bcls, float* __restrict__ out)
{
    const int b = blockIdx.x;
    const int tid = threadIdx.x;
    float mx = -INFINITY;
#pragma unroll
    for (int c = 0; c < 8; c++)
        mx = fmaxf(mx, part[((size_t)b * 8 + c) * DMODEL + tid]);
    __shared__ float sp[DMODEL];
    __shared__ float logits[NCLS];
    sp[tid] = mx;
    __syncthreads();
    if (tid < NCLS) {
        float s = bcls[tid];
        for (int d = 0; d < DMODEL; d++) s += Wcls[tid * DMODEL + d] * sp[d];
        logits[tid] = s;
    }
    __syncthreads();
    if (tid == 0) {
        float m = -INFINITY;
        for (int c = 0; c < NCLS; c++) m = fmaxf(m, logits[c]);
        float se = 0.f;
        for (int c = 0; c < NCLS; c++) se += expf(logits[c] - m);
        float lse = m + logf(se);
        for (int c = 0; c < NCLS; c++) out[b * NCLS + c] = logits[c] - lse;
    }
}

// ---------------- launch ----------------
extern "C" void kernel_launch(void* const* d_in, const int* in_sizes, int n_in,
                              void* d_out, int out_size)
{
    const float* x    = (const float*)d_in[0];
    const float* Wemb = (const float*)d_in[1];
    const float* bemb = (const float*)d_in[2];
    const float* Wqkv = (const float*)d_in[3];
    const float* bqkv = (const float*)d_in[4];
    const float* Wo   = (const float*)d_in[5];
    const float* bo   = (const float*)d_in[6];
    const float* W1   = (const float*)d_in[7];
    const float* b1f  = (const float*)d_in[8];
    const float* W2   = (const float*)d_in[9];
    const float* b2f  = (const float*)d_in[10];
    const float* g1   = (const float*)d_in[11];
    const float* be1  = (const float*)d_in[12];
    const float* g2   = (const float*)d_in[13];
    const float* be2  = (const float*)d_in[14];
    const float* Wcls = (const float*)d_in[15];
    const float* bcls = (const float*)d_in[16];

    float *pool;
    __half *x16, *h16, *o16, *qkv16, *attn16, *ff16, *wemb16, *wqkv16, *wo16, *wf1, *wf2;
    cudaGetSymbolAddress((void**)&pool,  g_pool);
    cudaGetSymbolAddress((void**)&x16,   g_x16);
    cudaGetSymbolAddress((void**)&h16,   g_h16);
    cudaGetSymbolAddress((void**)&o16,   g_o16);
    cudaGetSymbolAddress((void**)&qkv16, g_qkv16);
    cudaGetSymbolAddress((void**)&attn16,g_attn16);
    cudaGetSymbolAddress((void**)&ff16,  g_ff16);
    cudaGetSymbolAddress((void**)&wemb16,g_w16emb);
    cudaGetSymbolAddress((void**)&wqkv16,g_w16qkv);
    cudaGetSymbolAddress((void**)&wo16,  g_w16o);
    cudaGetSymbolAddress((void**)&wf1,   g_w16f1);
    cudaGetSymbolAddress((void**)&wf2,   g_w16f2);

    cudaFuncSetAttribute(hgemm_kernel,
                         cudaFuncAttributeMaxDynamicSharedMemorySize, HG_SMEM);

    const int GM = (MROWS + 127) / 128;  // 63

    // Launch order: attention(l=0) is launch #4 -> profiled by ncu.
    {
        int n0 = MROWS * INDIM;
        int n1 = DMODEL * INDIM;
        int n2 = NLAYER * 3 * DMODEL * DMODEL;
        int tot = n0 + n1 + n2;
        cvt3_kernel<<<(tot / 4 + 255) / 256, 256>>>(x, x16, n0, Wemb, wemb16, n1,
                                                    Wqkv, wqkv16, n2);
    }
    hgemm_kernel<<<dim3(GM, DMODEL / 128), 256, HG_SMEM>>>(
        x16, wemb16, bemb, h16, MROWS, DMODEL, INDIM, 2);
    hgemm_kernel<<<dim3(GM, (3 * DMODEL) / 128), 256, HG_SMEM>>>(
        h16, wqkv16, bqkv, qkv16, MROWS, 3 * DMODEL, DMODEL, 0);
    attn_mma_kernel<<<dim3(8, NHEAD, BSZ), 256>>>(qkv16, attn16);
    {
        int n0 = NLAYER * DMODEL * DMODEL;
        int n1 = NLAYER * FFDIM * DMODEL;
        int n2 = NLAYER * DMODEL * FFDIM;
        int tot = n0 + n1 + n2;
        cvt3_kernel<<<(tot / 4 + 255) / 256, 256>>>(Wo, wo16, n0, W1, wf1, n1, W2, wf2, n2);
    }

    for (int l = 0; l < NLAYER; l++) {
        if (l > 0) {
            hgemm_kernel<<<dim3(GM, (3 * DMODEL) / 128), 256, HG_SMEM>>>(
                h16, wqkv16 + (size_t)l * 3 * DMODEL * DMODEL,
                bqkv + (size_t)l * 3 * DMODEL, qkv16, MROWS, 3 * DMODEL, DMODEL, 0);
            attn_mma_kernel<<<dim3(8, NHEAD, BSZ), 256>>>(qkv16, attn16);
        }

        hgemm_kernel<<<dim3(GM, DMODEL / 128), 256, HG_SMEM>>>(
            attn16, wo16 + (size_t)l * DMODEL * DMODEL,
            bo + (size_t)l * DMODEL, o16, MROWS, DMODEL, DMODEL, 0);

        resln_kernel<<<MROWS / 8, 256>>>(h16, o16, g1 + (size_t)l * DMODEL,
                                         be1 + (size_t)l * DMODEL);

        hgemm_kernel<<<dim3(GM, FFDIM / 128), 256, HG_SMEM>>>(
            h16, wf1 + (size_t)l * FFDIM * DMODEL,
            b1f + (size_t)l * FFDIM, ff16, MROWS, FFDIM, DMODEL, 1);

        hgemm_kernel<<<dim3(GM, DMODEL / 128), 256, HG_SMEM>>>(
            ff16, wf2 + (size_t)l * DMODEL * FFDIM,
            b2f + (size_t)l * DMODEL, o16, MROWS, DMODEL, FFDIM, 0);

        resln_kernel<<<MROWS / 8, 256>>>(h16, o16, g2 + (size_t)l * DMODEL,
                                         be2 + (size_t)l * DMODEL);
    }

    pool_partial_kernel<<<dim3(BSZ, 8), 512>>>(h16, pool);
    pool_cls_kernel<<<BSZ, 512>>>(pool, Wcls, bcls, (float*)d_out);
}

// round 17
// speedup vs baseline: 1.5714x; 1.0163x over previous
#include <cuda_runtime.h>
#include <cuda_fp16.h>
#include <math.h>
#include <stdint.h>

#define BSZ    8
#define TT     1000
#define INDIM  256
#define DMODEL 512
#define FFDIM  2048
#define NLAYER 4
#define NHEAD  8
#define DHEAD  64
#define NCLS   8
#define MROWS  (BSZ*TT)   /* 8000 */

// ---------------- scratch (no cudaMalloc allowed) ----------------
__device__ float  g_pool[BSZ * 8 * DMODEL];

__device__ __half g_x16   [MROWS * INDIM];
__device__ __half g_h16   [MROWS * DMODEL];
__device__ __half g_o16   [MROWS * DMODEL];
__device__ __half g_qkv16 [MROWS * 3 * DMODEL];
__device__ __half g_attn16[MROWS * DMODEL];
__device__ __half g_ff16  [MROWS * FFDIM];

__device__ __half g_w16emb[DMODEL * INDIM];
__device__ __half g_w16qkv[NLAYER * 3 * DMODEL * DMODEL];
__device__ __half g_w16o  [NLAYER * DMODEL * DMODEL];
__device__ __half g_w16f1 [NLAYER * FFDIM * DMODEL];
__device__ __half g_w16f2 [NLAYER * DMODEL * FFDIM];

// ======================= helpers =======================
__device__ __forceinline__ uint32_t smem_u32(const void* p) {
    return (uint32_t)__cvta_generic_to_shared(p);
}
__device__ __forceinline__ uint32_t h2_u32(__half2 v) {
    return *reinterpret_cast<uint32_t*>(&v);
}
#define CP_ASYNC16(dst, src, pb) \
    asm volatile("cp.async.cg.shared.global [%0], [%1], 16, %2;\n" \
                 :: "r"(dst), "l"(src), "r"(pb))
#define CP_COMMIT() asm volatile("cp.async.commit_group;\n" ::: "memory")
#define CP_WAIT(n)  asm volatile("cp.async.wait_group %0;\n" :: "n"(n) : "memory")

#define LDSM_X4(r0,r1,r2,r3,addr) \
    asm volatile("ldmatrix.sync.aligned.m8n8.x4.shared.b16 {%0,%1,%2,%3}, [%4];" \
                 : "=r"(r0),"=r"(r1),"=r"(r2),"=r"(r3) : "r"(addr))
#define LDSM_X4T(r0,r1,r2,r3,addr) \
    asm volatile("ldmatrix.sync.aligned.m8n8.x4.trans.shared.b16 {%0,%1,%2,%3}, [%4];" \
                 : "=r"(r0),"=r"(r1),"=r"(r2),"=r"(r3) : "r"(addr))

__device__ __forceinline__ void mma16816(float c[4], uint32_t a0, uint32_t a1,
                                         uint32_t a2, uint32_t a3,
                                         uint32_t b0, uint32_t b1) {
    asm volatile(
        "mma.sync.aligned.m16n8k16.row.col.f32.f16.f16.f32 "
        "{%0,%1,%2,%3}, {%4,%5,%6,%7}, {%8,%9}, {%0,%1,%2,%3};"
        : "+f"(c[0]), "+f"(c[1]), "+f"(c[2]), "+f"(c[3])
        : "r"(a0), "r"(a1), "r"(a2), "r"(a3), "r"(b0), "r"(b1));
}

// ======================= fp16 HMMA GEMM =======================
// flags: 1 = relu, 2 = add sinusoidal PE (embedding). Output always fp16.
// K=64 per stage, 3 stages, prefetch distance 2, single __syncthreads/stage.
#define ROWB 144
#define STAGE_BYTES (128 * ROWB)          /* 18432 */
#define HG_SMEM (6 * STAGE_BYTES)         /* 110592 */

__global__ __launch_bounds__(256, 2)
void hgemm_kernel(const __half* __restrict__ A, const __half* __restrict__ W,
                  const float* __restrict__ bias, __half* __restrict__ Ch,
                  int M, int N, int K, int flags)
{
    extern __shared__ char smem[];
    const uint32_t sA = smem_u32(smem);
    const uint32_t sB = sA + 3 * STAGE_BYTES;

    const int tid  = threadIdx.x;
    const int wid  = tid >> 5;
    const int lane = tid & 31;
    const int wm = wid >> 2;
    const int wn = wid & 3;
    const int g   = lane >> 2;
    const int tig = lane & 3;
    const int m0 = blockIdx.x * 128;
    const int n0 = blockIdx.y * 128;

    const int nt = K >> 6;

    auto load_tile = [&](int t, int s) {
        const uint32_t da = sA + s * STAGE_BYTES;
        const uint32_t db = sB + s * STAGE_BYTES;
        const __half* Ak = A + t * 64;
        const __half* Wk = W + t * 64;
#pragma unroll
        for (int it = 0; it < 4; it++) {
            int id  = tid + it * 256;
            int row = id >> 3;
            int c   = id & 7;
            int ar = m0 + row; int arc = ar < M ? ar : (M - 1);
            int pa = (ar < M) ? 16 : 0;
            CP_ASYNC16(da + row * ROWB + c * 16,
                       (const char*)(Ak + (size_t)arc * K) + c * 16, pa);
            CP_ASYNC16(db + row * ROWB + c * 16,
                       (const char*)(Wk + (size_t)(n0 + row) * K) + c * 16, 16);
        }
        CP_COMMIT();
    };

    float acc[4][4][4];
#pragma unroll
    for (int i = 0; i < 4; i++)
#pragma unroll
        for (int j = 0; j < 4; j++)
#pragma unroll
            for (int r = 0; r < 4; r++) acc[i][j][r] = 0.f;

    load_tile(0, 0);
    load_tile(1, 1);

    const int a_row = (lane & 15);
    const int a_col = (lane >> 4) * 8;
    const int b_row = (lane & 7) + ((lane >> 4) << 3);
    const int b_col = ((lane >> 3) & 1) * 8;

    for (int kt = 0; kt < nt; kt++) {
        if (kt + 1 < nt) { CP_WAIT(1); } else { CP_WAIT(0); }
        __syncthreads();

        if (kt + 2 < nt) load_tile(kt + 2, (kt + 2) % 3);

        const int s = kt % 3;
        const uint32_t baseA = sA + s * STAGE_BYTES;
        const uint32_t baseB = sB + s * STAGE_BYTES;

#pragma unroll
        for (int ks = 0; ks < 4; ks++) {
            const int kk = ks * 16;
            uint32_t bf[4][2];
#pragma unroll
            for (int np = 0; np < 2; np++) {
                uint32_t addr = baseB
                    + (uint32_t)(wn * 32 + np * 16 + b_row) * ROWB
                    + (uint32_t)(kk + b_col) * 2;
                uint32_t b0, b1, b2, b3;
                LDSM_X4(b0, b1, b2, b3, addr);
                bf[np * 2 + 0][0] = b0; bf[np * 2 + 0][1] = b1;
                bf[np * 2 + 1][0] = b2; bf[np * 2 + 1][1] = b3;
            }
            uint32_t af[2][4];
            {
                uint32_t addr = baseA
                    + (uint32_t)(wm * 64 + 0 * 16 + a_row) * ROWB
                    + (uint32_t)(kk + a_col) * 2;
                LDSM_X4(af[0][0], af[0][1], af[0][2], af[0][3], addr);
            }
#pragma unroll
            for (int mi = 0; mi < 4; mi++) {
                if (mi < 3) {
                    uint32_t addr = baseA
                        + (uint32_t)(wm * 64 + (mi + 1) * 16 + a_row) * ROWB
                        + (uint32_t)(kk + a_col) * 2;
                    LDSM_X4(af[(mi + 1) & 1][0], af[(mi + 1) & 1][1],
                            af[(mi + 1) & 1][2], af[(mi + 1) & 1][3], addr);
                }
                const uint32_t* a = af[mi & 1];
#pragma unroll
                for (int ni = 0; ni < 4; ni++)
                    mma16816(acc[mi][ni], a[0], a[1], a[2], a[3],
                             bf[ni][0], bf[ni][1]);
            }
        }
    }

    const int relu  = flags & 1;
    const int addpe = flags & 2;
#pragma unroll
    for (int mi = 0; mi < 4; mi++) {
        int gr0 = m0 + wm * 64 + mi * 16 + g;
        int t0r = gr0 % TT, t1r = (gr0 + 8) % TT;
#pragma unroll
        for (int ni = 0; ni < 4; ni++) {
            int gc = n0 + wn * 32 + ni * 8 + 2 * tig;
            float b0 = bias[gc], b1 = bias[gc + 1];
            float v0 = acc[mi][ni][0] + b0;
            float v1 = acc[mi][ni][1] + b1;
            float v2 = acc[mi][ni][2] + b0;
            float v3 = acc[mi][ni][3] + b1;
            if (relu) {
                v0 = fmaxf(v0, 0.f); v1 = fmaxf(v1, 0.f);
                v2 = fmaxf(v2, 0.f); v3 = fmaxf(v3, 0.f);
            }
            if (addpe) {
                float div = expf((float)gc * (-9.210340371976184f / 512.0f));
                float s0, c0, s1, c1;
                sincosf((float)t0r * div, &s0, &c0);
                sincosf((float)t1r * div, &s1, &c1);
                v0 += s0; v1 += c0; v2 += s1; v3 += c1;
            }
            if (gr0 < M)
                *(__half2*)(Ch + (size_t)gr0 * N + gc) = __floats2half2_rn(v0, v1);
            if (gr0 + 8 < M)
                *(__half2*)(Ch + (size_t)(gr0 + 8) * N + gc) = __floats2half2_rn(v2, v3);
        }
    }
}

// ---------------- fused 3-tensor f32 -> f16 convert ----------------
__global__ void cvt3_kernel(const float* __restrict__ s0, __half* __restrict__ d0, int n0,
                            const float* __restrict__ s1, __half* __restrict__ d1, int n1,
                            const float* __restrict__ s2, __half* __restrict__ d2, int n2)
{
    int i = (blockIdx.x * blockDim.x + threadIdx.x) * 4;
    const float* s; __half* d;
    if (i < n0)           { s = s0; d = d0; }
    else if (i < n0 + n1) { s = s1; d = d1; i -= n0; }
    else if (i < n0 + n1 + n2) { s = s2; d = d2; i -= n0 + n1; }
    else return;
    float4 v = *(const float4*)(s + i);
    *(__half2*)(d + i)     = __floats2half2_rn(v.x, v.y);
    *(__half2*)(d + i + 2) = __floats2half2_rn(v.z, v.w);
}

// ================= HMMA banded flash attention (128 q / block) ============
// 64-key tiles, 3-slot ring (dynamic smem 73.7 KB), distance-2 prefetch,
// single __syncthreads per tile, per-warp tile skip, heavy heads first.
#define AT_STRIDE 72
#define AT_Q_BYTES   (128 * AT_STRIDE * 2)            /* 18432 */
#define AT_KV_BYTES  (64 * AT_STRIDE * 2)             /* 9216 per slot */
#define AT_SMEM      (AT_Q_BYTES + 6 * AT_KV_BYTES)   /* 73728 */

__global__ __launch_bounds__(256, 2)
void attn_mma_kernel(const __half* __restrict__ qkv, __half* __restrict__ out)
{
    extern __shared__ char asmem[];
    const uint32_t qbase = smem_u32(asmem);
    const uint32_t kbase = qbase + AT_Q_BYTES;                 // 3 slots
    const uint32_t vbase = kbase + 3 * AT_KV_BYTES;            // 3 slots

    const int b  = blockIdx.z;
    const int hh = (NHEAD - 1) - blockIdx.y;   // heavy heads first
    const int q0 = blockIdx.x * 128;
    const int tid  = threadIdx.x;
    const int warp = tid >> 5;
    const int lane = tid & 31;
    const int w = 25 * (hh + 1);

    int kstart = q0 - w;       if (kstart < 0) kstart = 0;
    int kend   = q0 + 127 + w; if (kend > TT - 1) kend = TT - 1;
    const int ntiles = (kend - kstart + 64) >> 6;

    const __half* base = qkv + (size_t)(b * TT) * 1536 + hh * 64;

    {
        for (int i = tid; i < 1024; i += 256) {
            int row = i >> 3, c = i & 7;
            int tq = q0 + row;
            int rc = tq < TT ? tq : (TT - 1);
            int pb = tq < TT ? 16 : 0;
            CP_ASYNC16(qbase + (row * AT_STRIDE + c * 8) * 2,
                       (const char*)(base + (size_t)rc * 1536 + c * 8), pb);
        }
    }
    auto stage_kv = [&](int t, int p) {
        const uint32_t kdst = kbase + p * AT_KV_BYTES;
        const uint32_t vdst = vbase + p * AT_KV_BYTES;
        const int j0 = kstart + t * 64;
#pragma unroll
        for (int it = 0; it < 2; it++) {
            int i = tid + it * 256;       // 0..511 covers 64 rows x 8 chunks
            int row = i >> 3, c = i & 7;
            int key = j0 + row;
            int rc = key < TT ? key : (TT - 1);
            int pb = key < TT ? 16 : 0;
            const __half* src = base + (size_t)rc * 1536 + c * 8;
            CP_ASYNC16(kdst + (row * AT_STRIDE + c * 8) * 2, (const char*)(src + 512),  pb);
            CP_ASYNC16(vdst + (row * AT_STRIDE + c * 8) * 2, (const char*)(src + 1024), pb);
        }
        CP_COMMIT();
    };

    stage_kv(0, 0);
    if (ntiles > 1) stage_kv(1, 1);

    const int r0 = lane >> 2;
    const int tq0 = q0 + warp * 16 + r0;
    const int tq1 = tq0 + 8;
    const int tqmin = q0 + warp * 16;
    const int tqmax = tqmin + 15;

    float mrun0 = -INFINITY, mrun1 = -INFINITY;
    float lsum0 = 0.f, lsum1 = 0.f;
    float O[8][4];
#pragma unroll
    for (int j = 0; j < 8; j++)
#pragma unroll
        for (int e = 0; e < 4; e++) O[j][e] = 0.f;

    uint32_t Qa[4][4];

    for (int t = 0; t < ntiles; t++) {
        if (t + 1 < ntiles) { CP_WAIT(1); } else { CP_WAIT(0); }
        __syncthreads();

        if (t + 2 < ntiles) stage_kv(t + 2, (t + 2) % 3);

        if (t == 0) {
#pragma unroll
            for (int ks = 0; ks < 4; ks++) {
                uint32_t addr = qbase + ((warp * 16 + (lane & 15)) * AT_STRIDE
                                         + ks * 16 + (lane >> 4) * 8) * 2;
                LDSM_X4(Qa[ks][0], Qa[ks][1], Qa[ks][2], Qa[ks][3], addr);
            }
        }

        const int j0 = kstart + t * 64;
        const int jlast = j0 + 63;

        const bool any_valid = !(j0 > tqmax + w) && !(jlast < tqmin - w)
                               && (j0 <= kend);
        if (!any_valid) continue;
        const bool full_valid = (j0 >= tqmax - w) && (jlast <= tqmin + w)
                                && (jlast <= kend);

        const int p = t % 3;
        const uint32_t kb = kbase + p * AT_KV_BYTES;
        const uint32_t vb = vbase + p * AT_KV_BYTES;

        float s[8][4];
#pragma unroll
        for (int j = 0; j < 8; j++)
#pragma unroll
            for (int e = 0; e < 4; e++) s[j][e] = 0.f;
#pragma unroll
        for (int ks = 0; ks < 4; ks++) {
#pragma unroll
            for (int jp = 0; jp < 4; jp++) {
                int row = jp * 16 + (lane & 7) + ((lane >> 4) << 3);
                int col = ks * 16 + ((lane >> 3) & 1) * 8;
                uint32_t addr = kb + (row * AT_STRIDE + col) * 2;
                uint32_t b0, b1, b2, b3;
                LDSM_X4(b0, b1, b2, b3, addr);
                mma16816(s[jp * 2 + 0], Qa[ks][0], Qa[ks][1], Qa[ks][2], Qa[ks][3], b0, b1);
                mma16816(s[jp * 2 + 1], Qa[ks][0], Qa[ks][1], Qa[ks][2], Qa[ks][3], b2, b3);
            }
        }

        if (full_valid) {
#pragma unroll
            for (int j = 0; j < 8; j++) {
                s[j][0] *= 0.125f; s[j][1] *= 0.125f;
                s[j][2] *= 0.125f; s[j][3] *= 0.125f;
            }
        } else {
#pragma unroll
            for (int j = 0; j < 8; j++) {
                int keyb = j0 + j * 8 + (lane & 3) * 2;
#pragma unroll
                for (int e = 0; e < 2; e++) {
                    int key = keyb + e;
                    int d0 = tq0 - key; d0 = d0 < 0 ? -d0 : d0;
                    int d1 = tq1 - key; d1 = d1 < 0 ? -d1 : d1;
                    bool kv = (key <= kend);
                    s[j][e]     = (kv && d0 <= w) ? s[j][e] * 0.125f     : -INFINITY;
                    s[j][2 + e] = (kv && d1 <= w) ? s[j][2 + e] * 0.125f : -INFINITY;
                }
            }
        }

        float mt0 = -INFINITY, mt1 = -INFINITY;
#pragma unroll
        for (int j = 0; j < 8; j++) {
            mt0 = fmaxf(mt0, fmaxf(s[j][0], s[j][1]));
            mt1 = fmaxf(mt1, fmaxf(s[j][2], s[j][3]));
        }
        mt0 = fmaxf(mt0, __shfl_xor_sync(0xffffffffu, mt0, 1));
        mt0 = fmaxf(mt0, __shfl_xor_sync(0xffffffffu, mt0, 2));
        mt1 = fmaxf(mt1, __shfl_xor_sync(0xffffffffu, mt1, 1));
        mt1 = fmaxf(mt1, __shfl_xor_sync(0xffffffffu, mt1, 2));

        float mnew0 = fmaxf(mrun0, mt0);
        float mnew1 = fmaxf(mrun1, mt1);
        float ms0 = (mnew0 == -INFINITY) ? 0.f : mnew0;
        float ms1 = (mnew1 == -INFINITY) ? 0.f : mnew1;
        float alpha0 = __expf(mrun0 - ms0);
        float alpha1 = __expf(mrun1 - ms1);
        mrun0 = mnew0; mrun1 = mnew1;

        float ls0 = 0.f, ls1 = 0.f;
#pragma unroll
        for (int j = 0; j < 8; j++) {
            s[j][0] = __expf(s[j][0] - ms0);
            s[j][1] = __expf(s[j][1] - ms0);
            s[j][2] = __expf(s[j][2] - ms1);
            s[j][3] = __expf(s[j][3] - ms1);
            ls0 += s[j][0] + s[j][1];
            ls1 += s[j][2] + s[j][3];
        }
        ls0 += __shfl_xor_sync(0xffffffffu, ls0, 1);
        ls0 += __shfl_xor_sync(0xffffffffu, ls0, 2);
        ls1 += __shfl_xor_sync(0xffffffffu, ls1, 1);
        ls1 += __shfl_xor_sync(0xffffffffu, ls1, 2);
        lsum0 = lsum0 * alpha0 + ls0;
        lsum1 = lsum1 * alpha1 + ls1;

#pragma unroll
        for (int j = 0; j < 8; j++) {
            O[j][0] *= alpha0; O[j][1] *= alpha0;
            O[j][2] *= alpha1; O[j][3] *= alpha1;
        }

        uint32_t aP[4][4];
#pragma unroll
        for (int s2 = 0; s2 < 4; s2++) {
            aP[s2][0] = h2_u32(__floats2half2_rn(s[s2 * 2][0],     s[s2 * 2][1]));
            aP[s2][1] = h2_u32(__floats2half2_rn(s[s2 * 2][2],     s[s2 * 2][3]));
            aP[s2][2] = h2_u32(__floats2half2_rn(s[s2 * 2 + 1][0], s[s2 * 2 + 1][1]));
            aP[s2][3] = h2_u32(__floats2half2_rn(s[s2 * 2 + 1][2], s[s2 * 2 + 1][3]));
        }

#pragma unroll
        for (int s2 = 0; s2 < 4; s2++) {
#pragma unroll
            for (int jp = 0; jp < 4; jp++) {
                int row = s2 * 16 + (lane & 15);
                int col = jp * 16 + ((lane >> 4) << 3);
                uint32_t addr = vb + (row * AT_STRIDE + col) * 2;
                uint32_t b0, b1, b2, b3;
                LDSM_X4T(b0, b1, b2, b3, addr);
                mma16816(O[jp * 2 + 0], aP[s2][0], aP[s2][1], aP[s2][2], aP[s2][3], b0, b1);
                mma16816(O[jp * 2 + 1], aP[s2][0], aP[s2][1], aP[s2][2], aP[s2][3], b2, b3);
            }
        }
    }

    float inv0 = 1.0f / lsum0;
    float inv1 = 1.0f / lsum1;
    const int coff = hh * 64 + (lane & 3) * 2;
    if (tq0 < TT) {
        __half* op = out + (size_t)(b * TT + tq0) * DMODEL + coff;
#pragma unroll
        for (int j = 0; j < 8; j++)
            *(__half2*)(op + j * 8) = __floats2half2_rn(O[j][0] * inv0, O[j][1] * inv0);
    }
    if (tq1 < TT) {
        __half* op = out + (size_t)(b * TT + tq1) * DMODEL + coff;
#pragma unroll
        for (int j = 0; j < 8; j++)
            *(__half2*)(op + j * 8) = __floats2half2_rn(O[j][2] * inv1, O[j][3] * inv1);
    }
}

// ------- residual + LayerNorm: one warp per row, warp-local reduce -------
__global__ __launch_bounds__(256)
void resln_kernel(__half* __restrict__ h16, const __half* __restrict__ o16,
                  const float* __restrict__ g, const float* __restrict__ be)
{
    const int row  = blockIdx.x * 8 + (threadIdx.x >> 5);
    const int lane = threadIdx.x & 31;

    const uint4* hp = (const uint4*)(h16 + (size_t)row * DMODEL);
    const uint4* op = (const uint4*)(o16 + (size_t)row * DMODEL);
    uint4 hv[2], ov[2];
    hv[0] = hp[lane]; hv[1] = hp[lane + 32];
    ov[0] = op[lane]; ov[1] = op[lane + 32];

    float x[16];
#pragma unroll
    for (int q = 0; q < 2; q++) {
        const uint32_t* hw = (const uint32_t*)&hv[q];
        const uint32_t* ow = (const uint32_t*)&ov[q];
#pragma unroll
        for (int k = 0; k < 4; k++) {
            __half2 hh2 = *(const __half2*)&hw[k];
            __half2 oo2 = *(const __half2*)&ow[k];
            float2 hf = __half22float2(hh2);
            float2 of = __half22float2(oo2);
            x[q * 8 + k * 2 + 0] = hf.x + of.x;
            x[q * 8 + k * 2 + 1] = hf.y + of.y;
        }
    }

    float s = 0.f, sq = 0.f;
#pragma unroll
    for (int k = 0; k < 16; k++) { s += x[k]; sq += x[k] * x[k]; }
#pragma unroll
    for (int off = 16; off > 0; off >>= 1) {
        s  += __shfl_xor_sync(0xffffffffu, s, off);
        sq += __shfl_xor_sync(0xffffffffu, sq, off);
    }
    float mean = s * (1.0f / 512.0f);
    float var  = sq * (1.0f / 512.0f) - mean * mean;
    float r = rsqrtf(var + 1e-5f);

    uint4* wp = (uint4*)(h16 + (size_t)row * DMODEL);
#pragma unroll
    for (int q = 0; q < 2; q++) {
        int e0 = (q * 32 + lane) * 8;
        float4 g0 = *(const float4*)(g + e0);
        float4 g1 = *(const float4*)(g + e0 + 4);
        float4 b0 = *(const float4*)(be + e0);
        float4 b1 = *(const float4*)(be + e0 + 4);
        uint4 outv;
        uint32_t* owp = (uint32_t*)&outv;
        float y0 = (x[q*8+0] - mean) * r * g0.x + b0.x;
        float y1 = (x[q*8+1] - mean) * r * g0.y + b0.y;
        owp[0] = h2_u32(__floats2half2_rn(y0, y1));
        y0 = (x[q*8+2] - mean) * r * g0.z + b0.z;
        y1 = (x[q*8+3] - mean) * r * g0.w + b0.w;
        owp[1] = h2_u32(__floats2half2_rn(y0, y1));
        y0 = (x[q*8+4] - mean) * r * g1.x + b1.x;
        y1 = (x[q*8+5] - mean) * r * g1.y + b1.y;
        owp[2] = h2_u32(__floats2half2_rn(y0, y1));
        y0 = (x[q*8+6] - mean) * r * g1.z + b1.z;
        y1 = (x[q*8+7] - mean) * r * g1.w + b1.w;
        owp[3] = h2_u32(__floats2half2_rn(y0, y1));
        wp[q * 32 + lane] = outv;
    }
}

// ---------------- pooling ----------
__global__ __launch_bounds__(512)
void pool_partial_kernel(const __half* __restrict__ h16, float* __restrict__ part)
{
    const int b = blockIdx.x;
    const int c = blockIdx.y;
    const int tid = threadIdx.x;
    const int t0 = c * 125;
    float mx = -INFINITY;
    for (int t = t0; t < t0 + 125; t++)
        mx = fmaxf(mx, __half2float(h16[((size_t)b * TT + t) * DMODEL + tid]));
    part[((size_t)b * 8 + c) * DMODEL + tid] = mx;
}

__global__ __launch_bounds__(512)
void pool_cls_kernel(const float* __restrict__ part, const float* __restrict__ Wcls,
                     const float* __restrict__ bcls, float* __restrict__ out)
{
    const int b = blockIdx.x;
    const int tid = threadIdx.x;
    float mx = -INFINITY;
#pragma unroll
    for (int c = 0; c < 8; c++)
        mx = fmaxf(mx, part[((size_t)b * 8 + c) * DMODEL + tid]);
    __shared__ float sp[DMODEL];
    __shared__ float logits[NCLS];
    sp[tid] = mx;
    __syncthreads();
    if (tid < NCLS) {
        float s = bcls[tid];
        for (int d = 0; d < DMODEL; d++) s += Wcls[tid * DMODEL + d] * sp[d];
        logits[tid] = s;
    }
    __syncthreads();
    if (tid == 0) {
        float m = -INFINITY;
        for (int c = 0; c < NCLS; c++) m = fmaxf(m, logits[c]);
        float se = 0.f;
        for (int c = 0; c < NCLS; c++) se += expf(logits[c] - m);
        float lse = m + logf(se);
        for (int c = 0; c < NCLS; c++) out[b * NCLS + c] = logits[c] - lse;
    }
}

// ---------------- launch ----------------
extern "C" void kernel_launch(void* const* d_in, const int* in_sizes, int n_in,
                              void* d_out, int out_size)
{
    const float* x    = (const float*)d_in[0];
    const float* Wemb = (const float*)d_in[1];
    const float* bemb = (const float*)d_in[2];
    const float* Wqkv = (const float*)d_in[3];
    const float* bqkv = (const float*)d_in[4];
    const float* Wo   = (const float*)d_in[5];
    const float* bo   = (const float*)d_in[6];
    const float* W1   = (const float*)d_in[7];
    const float* b1f  = (const float*)d_in[8];
    const float* W2   = (const float*)d_in[9];
    const float* b2f  = (const float*)d_in[10];
    const float* g1   = (const float*)d_in[11];
    const float* be1  = (const float*)d_in[12];
    const float* g2   = (const float*)d_in[13];
    const float* be2  = (const float*)d_in[14];
    const float* Wcls = (const float*)d_in[15];
    const float* bcls = (const float*)d_in[16];

    float *pool;
    __half *x16, *h16, *o16, *qkv16, *attn16, *ff16, *wemb16, *wqkv16, *wo16, *wf1, *wf2;
    cudaGetSymbolAddress((void**)&pool,  g_pool);
    cudaGetSymbolAddress((void**)&x16,   g_x16);
    cudaGetSymbolAddress((void**)&h16,   g_h16);
    cudaGetSymbolAddress((void**)&o16,   g_o16);
    cudaGetSymbolAddress((void**)&qkv16, g_qkv16);
    cudaGetSymbolAddress((void**)&attn16,g_attn16);
    cudaGetSymbolAddress((void**)&ff16,  g_ff16);
    cudaGetSymbolAddress((void**)&wemb16,g_w16emb);
    cudaGetSymbolAddress((void**)&wqkv16,g_w16qkv);
    cudaGetSymbolAddress((void**)&wo16,  g_w16o);
    cudaGetSymbolAddress((void**)&wf1,   g_w16f1);
    cudaGetSymbolAddress((void**)&wf2,   g_w16f2);

    cudaFuncSetAttribute(hgemm_kernel,
                         cudaFuncAttributeMaxDynamicSharedMemorySize, HG_SMEM);
    cudaFuncSetAttribute(attn_mma_kernel,
                         cudaFuncAttributeMaxDynamicSharedMemorySize, AT_SMEM);

    const int GM = (MROWS + 127) / 128;  // 63

    // Launch order: attention(l=0) is launch #4 -> profiled by ncu.
    {
        int n0 = MROWS * INDIM;
        int n1 = DMODEL * INDIM;
        int n2 = NLAYER * 3 * DMODEL * DMODEL;
        int tot = n0 + n1 + n2;
        cvt3_kernel<<<(tot / 4 + 255) / 256, 256>>>(x, x16, n0, Wemb, wemb16, n1,
                                                    Wqkv, wqkv16, n2);
    }
    hgemm_kernel<<<dim3(GM, DMODEL / 128), 256, HG_SMEM>>>(
        x16, wemb16, bemb, h16, MROWS, DMODEL, INDIM, 2);
    hgemm_kernel<<<dim3(GM, (3 * DMODEL) / 128), 256, HG_SMEM>>>(
        h16, wqkv16, bqkv, qkv16, MROWS, 3 * DMODEL, DMODEL, 0);
    attn_mma_kernel<<<dim3(8, NHEAD, BSZ), 256, AT_SMEM>>>(qkv16, attn16);
    {
        int n0 = NLAYER * DMODEL * DMODEL;
        int n1 = NLAYER * FFDIM * DMODEL;
        int n2 = NLAYER * DMODEL * FFDIM;
        int tot = n0 + n1 + n2;
        cvt3_kernel<<<(tot / 4 + 255) / 256, 256>>>(Wo, wo16, n0, W1, wf1, n1, W2, wf2, n2);
    }

    for (int l = 0; l < NLAYER; l++) {
        if (l > 0) {
            hgemm_kernel<<<dim3(GM, (3 * DMODEL) / 128), 256, HG_SMEM>>>(
                h16, wqkv16 + (size_t)l * 3 * DMODEL * DMODEL,
                bqkv + (size_t)l * 3 * DMODEL, qkv16, MROWS, 3 * DMODEL, DMODEL, 0);
            attn_mma_kernel<<<dim3(8, NHEAD, BSZ), 256, AT_SMEM>>>(qkv16, attn16);
        }

        hgemm_kernel<<<dim3(GM, DMODEL / 128), 256, HG_SMEM>>>(
            attn16, wo16 + (size_t)l * DMODEL * DMODEL,
            bo + (size_t)l * DMODEL, o16, MROWS, DMODEL, DMODEL, 0);

        resln_kernel<<<MROWS / 8, 256>>>(h16, o16, g1 + (size_t)l * DMODEL,
                                         be1 + (size_t)l * DMODEL);

        hgemm_kernel<<<dim3(GM, FFDIM / 128), 256, HG_SMEM>>>(
            h16, wf1 + (size_t)l * FFDIM * DMODEL,
            b1f + (size_t)l * FFDIM, ff16, MROWS, FFDIM, DMODEL, 1);

        hgemm_kernel<<<dim3(GM, DMODEL / 128), 256, HG_SMEM>>>(
            ff16, wf2 + (size_t)l * DMODEL * FFDIM,
            b2f + (size_t)l * DMODEL, o16, MROWS, DMODEL, FFDIM, 0);

        resln_kernel<<<MROWS / 8, 256>>>(h16, o16, g2 + (size_t)l * DMODEL,
                                         be2 + (size_t)l * DMODEL);
    }

    pool_partial_kernel<<<dim3(BSZ, 8), 512>>>(h16, pool);
    pool_cls_kernel<<<BSZ, 512>>>(pool, Wcls, bcls, (float*)d_out);
}